// round 1
// baseline (speedup 1.0000x reference)
#include <cuda_runtime.h>
#include <cuda_bf16.h>
#include <math.h>

// Problem constants
#define BB   2
#define CC   256
#define EE   32
#define HH   48
#define WW   48
#define DD   48
#define WD   2304      // W*D
#define HWD  110592    // H*W*D
#define NP   221184    // B*HWD
#define NL   144       // 3*48 logits per position

// ---------------------------------------------------------------------------
// Scratch (device globals: allocation-free rule)
// ---------------------------------------------------------------------------
__device__ float g_q  [(size_t)NP * EE];   // (B,HWD,32)  28.3 MB
__device__ float g_k  [(size_t)NP * EE];   // (B,HWD,32)  28.3 MB
__device__ float g_v  [(size_t)NP * CC];   // (B,HWD,256) 226.5 MB
__device__ float g_att[(size_t)NP * NL];   // (B,HWD,144) 127.4 MB
__device__ float g_acc[(size_t)NP * CC];   // (B,HWD,256) 226.5 MB

// ---------------------------------------------------------------------------
// Kernel 1: fused QKV projection.
// out[o,p] = sum_c W[o,c]*query[b,c,p] + bias[o], o in [0,320)
//   o 0..31  -> q  (Wq,bq)   o 32..63 -> k (Wk,bk)   o 64..319 -> v (Wv,bv)
// grid: (5 output-groups of 64, 864 position tiles of 128, B)
// block 256 = 16(tx: 4 outputs) x 16(ty: 8 positions stride 16)
// ---------------------------------------------------------------------------
__global__ __launch_bounds__(256) void proj_kernel(
    const float* __restrict__ query,
    const float* __restrict__ Wq, const float* __restrict__ bq,
    const float* __restrict__ Wk, const float* __restrict__ bk,
    const float* __restrict__ Wv, const float* __restrict__ bv)
{
    const int g     = blockIdx.x;          // output group 0..4
    const int pbase = blockIdx.y * 128;    // position tile
    const int b     = blockIdx.z;
    const int tid   = threadIdx.x;
    const int tx    = tid & 15;            // output within group: o = g*64 + tx*4
    const int ty    = tid >> 4;            // position: p = pbase + ty + 16*i

    __shared__ float Xs[32][132];          // padded (132) query chunk [c][p]
    __shared__ float Ws[32][64];           // weight chunk [c][o]

    float acc[8][4];
    {
        const int o0 = g * 64 + tx * 4;
        float b4[4];
        #pragma unroll
        for (int j = 0; j < 4; j++) {
            const int o = o0 + j;
            b4[j] = (o < 32) ? bq[o] : (o < 64) ? bk[o - 32] : bv[o - 64];
        }
        #pragma unroll
        for (int i = 0; i < 8; i++)
            #pragma unroll
            for (int j = 0; j < 4; j++) acc[i][j] = b4[j];
    }

    const float* Xg = query + (size_t)b * CC * HWD + pbase;

    for (int cc0 = 0; cc0 < CC; cc0 += 32) {
        // load X chunk: 32 c x 128 p (1024 float4)
        #pragma unroll
        for (int k = 0; k < 4; k++) {
            const int f  = tid + k * 256;
            const int cc = f >> 5;
            const int p4 = f & 31;
            float4 v = *(const float4*)(Xg + (size_t)(cc0 + cc) * HWD + p4 * 4);
            *(float4*)&Xs[cc][p4 * 4] = v;
        }
        // load W chunk: Ws[cc][o]
        {
            const int o     = tid & 63;
            const int cbase = (tid >> 6) * 8;
            const int og    = g * 64 + o;
            const float* Wrow = (og < 32) ? (Wq + og * 256)
                              : (og < 64) ? (Wk + (og - 32) * 256)
                                          : (Wv + (size_t)(og - 64) * 256);
            #pragma unroll
            for (int i = 0; i < 8; i++)
                Ws[cbase + i][o] = Wrow[cc0 + cbase + i];
        }
        __syncthreads();

        #pragma unroll
        for (int cc = 0; cc < 32; cc++) {
            const float4 w4 = *(const float4*)&Ws[cc][tx * 4];
            #pragma unroll
            for (int i = 0; i < 8; i++) {
                const float xv = Xs[cc][ty + 16 * i];
                acc[i][0] += xv * w4.x;
                acc[i][1] += xv * w4.y;
                acc[i][2] += xv * w4.z;
                acc[i][3] += xv * w4.w;
            }
        }
        __syncthreads();
    }

    // write results (position-major layouts)
    #pragma unroll
    for (int i = 0; i < 8; i++) {
        const int p = pbase + ty + 16 * i;
        const size_t pp = (size_t)b * HWD + p;
        const float4 r = make_float4(acc[i][0], acc[i][1], acc[i][2], acc[i][3]);
        if (g == 0) {
            if (tx < 8) *(float4*)&g_q[pp * EE + tx * 4]        = r;
            else        *(float4*)&g_k[pp * EE + (tx - 8) * 4]  = r;
        } else {
            *(float4*)&g_v[pp * CC + (g - 1) * 64 + tx * 4] = r;
        }
    }
}

// ---------------------------------------------------------------------------
// Kernel 2: logits per axis. One block = one 48-long line.
// eH masked with -3e38 on the diagonal (reference masks only eH).
// grid: (2304 lines, 3 axes, B)
// ---------------------------------------------------------------------------
__global__ __launch_bounds__(256) void logits_kernel()
{
    const int l    = blockIdx.x;
    const int axis = blockIdx.y;
    const int b    = blockIdx.z;
    const int tid  = threadIdx.x;

    __shared__ float Qs[48][32];
    __shared__ float Ks[48][32];

    const int a1 = l / 48, a2 = l % 48;
    int base, stride;
    if      (axis == 0) { base = a1 * 48 + a2;        stride = WD; }  // (w,d), x over H
    else if (axis == 1) { base = a1 * WD + a2;        stride = 48; }  // (h,d), y over W
    else                { base = a1 * WD + a2 * 48;   stride = 1;  }  // (h,w), y over D

    const size_t b0 = (size_t)b * HWD;

    for (int f = tid; f < 48 * 32; f += 256) {
        const int y = f >> 5, e = f & 31;
        const size_t p = b0 + base + (size_t)y * stride;
        Qs[y][e] = g_q[p * EE + e];
        Ks[y][e] = g_k[p * EE + e];
    }
    __syncthreads();

    #pragma unroll
    for (int k = 0; k < 9; k++) {
        const int id = tid + k * 256;  // 2304 pairs
        const int x = id / 48, y = id % 48;
        float s = 0.f;
        #pragma unroll
        for (int e = 0; e < 32; e++) s += Qs[x][e] * Ks[y][e];
        if (axis == 0 && x == y) s = -3.0e38f;
        const size_t p = b0 + base + (size_t)x * stride;
        g_att[p * NL + axis * 48 + y] = s;
    }
}

// ---------------------------------------------------------------------------
// Kernel 3: softmax over 144 per position. 8 lanes per position, 32 pos/block.
// grid: NP/32 = 6912
// ---------------------------------------------------------------------------
__global__ __launch_bounds__(256) void softmax_kernel()
{
    const int tid  = threadIdx.x;
    const int pos  = blockIdx.x * 32 + (tid >> 3);
    const int lane = tid & 7;
    float* row = g_att + (size_t)pos * NL;

    float4 v[5];
    float m = -3.4e38f;
    #pragma unroll
    for (int k = 0; k < 5; k++) {
        const int j = lane + k * 8;
        if (j < 36) {
            v[k] = *(const float4*)&row[j * 4];
            m = fmaxf(m, fmaxf(fmaxf(v[k].x, v[k].y), fmaxf(v[k].z, v[k].w)));
        }
    }
    #pragma unroll
    for (int o = 1; o < 8; o <<= 1)
        m = fmaxf(m, __shfl_xor_sync(0xffffffffu, m, o));

    float s = 0.f;
    #pragma unroll
    for (int k = 0; k < 5; k++) {
        const int j = lane + k * 8;
        if (j < 36) {
            v[k].x = expf(v[k].x - m);
            v[k].y = expf(v[k].y - m);
            v[k].z = expf(v[k].z - m);
            v[k].w = expf(v[k].w - m);
            s += v[k].x + v[k].y + v[k].z + v[k].w;
        }
    }
    #pragma unroll
    for (int o = 1; o < 8; o <<= 1)
        s += __shfl_xor_sync(0xffffffffu, s, o);

    const float inv = 1.f / s;
    #pragma unroll
    for (int k = 0; k < 5; k++) {
        const int j = lane + k * 8;
        if (j < 36) {
            v[k].x *= inv; v[k].y *= inv; v[k].z *= inv; v[k].w *= inv;
            *(float4*)&row[j * 4] = v[k];
        }
    }
}

// ---------------------------------------------------------------------------
// Kernel 4/5/6: aggregation per axis. One block = one line.
//   out_line[x][c] = sum_y A[x][y] * V[y][c]   (48x48 @ 48x256)
// AXIS 0: write g_acc.  AXIS 1: g_acc +=.  AXIS 2: fused final epilogue
//   out = gamma*(acc + local) + query   (D-axis positions are contiguous).
// dynamic smem: Vs[48][256] + As[48][48] = 58368 B
// ---------------------------------------------------------------------------
template<int AXIS>
__global__ __launch_bounds__(256) void agg_kernel(
    const float* __restrict__ query,
    const float* __restrict__ gamma,
    float* __restrict__ out)
{
    extern __shared__ float sm[];
    float (*Vs)[256] = (float (*)[256])sm;             // 48x256
    float (*As)[48]  = (float (*)[48])(sm + 48 * 256); // 48x48

    const int l   = blockIdx.x;
    const int b   = blockIdx.y;
    const int tid = threadIdx.x;

    const int a1 = l / 48, a2 = l % 48;
    int base, stride;
    if      (AXIS == 0) { base = a1 * 48 + a2;      stride = WD; }
    else if (AXIS == 1) { base = a1 * WD + a2;      stride = 48; }
    else                { base = a1 * WD + a2 * 48; stride = 1;  }

    const size_t b0 = (size_t)b * HWD;

    // load V line (48 x 256)
    #pragma unroll
    for (int k = 0; k < 12; k++) {
        const int f  = tid + k * 256;   // float4 id, 3072 total
        const int y  = f >> 6;
        const int c4 = f & 63;
        *(float4*)&Vs[y][c4 * 4] =
            *(const float4*)&g_v[(b0 + base + (size_t)y * stride) * CC + c4 * 4];
    }
    // load A (48 x 48)
    #pragma unroll
    for (int k = 0; k < 9; k++) {
        const int f = tid + k * 256;
        const int x = f / 48, y = f % 48;
        As[x][y] = g_att[(b0 + base + (size_t)x * stride) * NL + AXIS * 48 + y];
    }
    __syncthreads();

    const int cg = tid & 31,  c0 = cg * 8;   // 8 channels
    const int xg = tid >> 5,  x0 = xg * 6;   // 6 x values

    float acc[6][8];
    #pragma unroll
    for (int i = 0; i < 6; i++)
        #pragma unroll
        for (int j = 0; j < 8; j++) acc[i][j] = 0.f;

    #pragma unroll 2
    for (int y = 0; y < 48; y++) {
        const float4 v0 = *(const float4*)&Vs[y][c0];
        const float4 v1 = *(const float4*)&Vs[y][c0 + 4];
        #pragma unroll
        for (int xi = 0; xi < 6; xi++) {
            const float a = As[x0 + xi][y];
            acc[xi][0] += a * v0.x; acc[xi][1] += a * v0.y;
            acc[xi][2] += a * v0.z; acc[xi][3] += a * v0.w;
            acc[xi][4] += a * v1.x; acc[xi][5] += a * v1.y;
            acc[xi][6] += a * v1.z; acc[xi][7] += a * v1.w;
        }
    }

    if (AXIS == 0) {
        #pragma unroll
        for (int xi = 0; xi < 6; xi++) {
            const size_t p = b0 + base + (size_t)(x0 + xi) * stride;
            *(float4*)&g_acc[p * CC + c0]     = make_float4(acc[xi][0], acc[xi][1], acc[xi][2], acc[xi][3]);
            *(float4*)&g_acc[p * CC + c0 + 4] = make_float4(acc[xi][4], acc[xi][5], acc[xi][6], acc[xi][7]);
        }
    } else if (AXIS == 1) {
        #pragma unroll
        for (int xi = 0; xi < 6; xi++) {
            const size_t p = b0 + base + (size_t)(x0 + xi) * stride;
            float4 a0 = *(const float4*)&g_acc[p * CC + c0];
            float4 a1 = *(const float4*)&g_acc[p * CC + c0 + 4];
            a0.x += acc[xi][0]; a0.y += acc[xi][1]; a0.z += acc[xi][2]; a0.w += acc[xi][3];
            a1.x += acc[xi][4]; a1.y += acc[xi][5]; a1.z += acc[xi][6]; a1.w += acc[xi][7];
            *(float4*)&g_acc[p * CC + c0]     = a0;
            *(float4*)&g_acc[p * CC + c0 + 4] = a1;
        }
    } else {
        // total = g_acc + local; stage via smem (reuse Vs) for a transposed,
        // coalesced epilogue in the channel-major output layout.
        __syncthreads();
        float (*Rs)[256] = Vs;
        #pragma unroll
        for (int xi = 0; xi < 6; xi++) {
            const int x = x0 + xi;
            const size_t p = b0 + base + x;       // stride 1
            const float4 a0 = *(const float4*)&g_acc[p * CC + c0];
            const float4 a1 = *(const float4*)&g_acc[p * CC + c0 + 4];
            Rs[x][c0 + 0] = acc[xi][0] + a0.x;  Rs[x][c0 + 1] = acc[xi][1] + a0.y;
            Rs[x][c0 + 2] = acc[xi][2] + a0.z;  Rs[x][c0 + 3] = acc[xi][3] + a0.w;
            Rs[x][c0 + 4] = acc[xi][4] + a1.x;  Rs[x][c0 + 5] = acc[xi][5] + a1.y;
            Rs[x][c0 + 6] = acc[xi][6] + a1.z;  Rs[x][c0 + 7] = acc[xi][7] + a1.w;
        }
        __syncthreads();

        const float gm = gamma[0];
        const int c = tid;                        // 256 threads = 256 channels
        const size_t gidx = ((size_t)b * CC + c) * HWD + base;
        #pragma unroll 4
        for (int x = 0; x < 48; x++) {
            out[gidx + x] = gm * Rs[x][c] + query[gidx + x];
        }
    }
}

// ---------------------------------------------------------------------------
extern "C" void kernel_launch(void* const* d_in, const int* in_sizes, int n_in,
                              void* d_out, int out_size)
{
    const float* query = (const float*)d_in[0];
    const float* Wq    = (const float*)d_in[1];
    const float* bq    = (const float*)d_in[2];
    const float* Wk    = (const float*)d_in[3];
    const float* bk    = (const float*)d_in[4];
    const float* Wv    = (const float*)d_in[5];
    const float* bv    = (const float*)d_in[6];
    const float* gamma = (const float*)d_in[7];
    float* out = (float*)d_out;

    const int AGG_SMEM = (48 * 256 + 48 * 48) * 4;  // 58368 B
    cudaFuncSetAttribute(agg_kernel<0>, cudaFuncAttributeMaxDynamicSharedMemorySize, AGG_SMEM);
    cudaFuncSetAttribute(agg_kernel<1>, cudaFuncAttributeMaxDynamicSharedMemorySize, AGG_SMEM);
    cudaFuncSetAttribute(agg_kernel<2>, cudaFuncAttributeMaxDynamicSharedMemorySize, AGG_SMEM);

    proj_kernel   <<<dim3(5, 864, BB), 256>>>(query, Wq, bq, Wk, bk, Wv, bv);
    logits_kernel <<<dim3(WD, 3, BB), 256>>>();
    softmax_kernel<<<NP / 32, 256>>>();
    agg_kernel<0> <<<dim3(WD, BB), 256, AGG_SMEM>>>(query, gamma, out);
    agg_kernel<1> <<<dim3(WD, BB), 256, AGG_SMEM>>>(query, gamma, out);
    agg_kernel<2> <<<dim3(WD, BB), 256, AGG_SMEM>>>(query, gamma, out);
}

// round 3
// speedup vs baseline: 1.1568x; 1.1568x over previous
#include <cuda_runtime.h>
#include <cuda_bf16.h>
#include <math.h>
#include <stdint.h>

// Problem constants
#define BB   2
#define CC   256
#define EE   32
#define HH   48
#define WD   2304      // W*D
#define HWD  110592    // H*W*D
#define NP   221184    // B*HWD
#define NL   144       // 3*48 logits per position

// ---------------------------------------------------------------------------
// Scratch (device globals: allocation-free rule)
// ---------------------------------------------------------------------------
__device__ float    g_q  [(size_t)NP * EE];   // (NP,32)
__device__ float    g_k  [(size_t)NP * EE];   // (NP,32)
__device__ float    g_v  [(size_t)NP * CC];   // (NP,256)
__device__ float    g_att[(size_t)NP * NL];   // raw logits (NP,144)
__device__ float2   g_mz [(size_t)NP];        // per-position (max, 1/sum)
__device__ float    g_acc[(size_t)NP * CC];   // partial sums (NP,256)
__device__ uint32_t g_wvh[256 * 256];         // Wv hi (tf32 bits)
__device__ uint32_t g_wvl[256 * 256];         // Wv lo (tf32 bits)

__device__ __forceinline__ uint32_t cvt_tf32(float x) {
    uint32_t r;
    asm("cvt.rna.tf32.f32 %0, %1;" : "=r"(r) : "f"(x));
    return r;
}

// ---------------------------------------------------------------------------
// Kernel 0: split Wv into tf32 hi/lo (one-time prep, trivial cost)
// ---------------------------------------------------------------------------
__global__ __launch_bounds__(256) void wv_split_kernel(const float* __restrict__ Wv)
{
    const int i = blockIdx.x * 256 + threadIdx.x;
    const float w = Wv[i];
    const uint32_t h = cvt_tf32(w);
    g_wvh[i] = h;
    g_wvl[i] = cvt_tf32(w - __uint_as_float(h));
}

// ---------------------------------------------------------------------------
// Kernel 1: fused QKV projection, single pass over query.
//   out[o,p] = sum_c W[o,c]*X[c,p] + bias[o]
// Block: 64 positions x all 320 outputs. K chunks of 32.
// V (256 outputs) via 3xTF32 mma.sync m16n8k8 (fp32-accurate).
// Q/K (64 outputs) via fp32 FFMA.
// smem: Xs[32][72] + Wvh[256][36] + Wvl[256][36] + Wqks[32][68] = 91648 B
// ---------------------------------------------------------------------------
__global__ __launch_bounds__(256, 2) void proj_kernel(
    const float* __restrict__ query,
    const float* __restrict__ Wq, const float* __restrict__ bq,
    const float* __restrict__ Wk, const float* __restrict__ bk,
    const float* __restrict__ bv)
{
    extern __shared__ float sm[];
    float    (*Xs)[72]   = (float (*)[72])sm;                          // [k][p]
    uint32_t (*Wvh)[36]  = (uint32_t (*)[36])(sm + 32 * 72);           // [o][k]
    uint32_t (*Wvl)[36]  = (uint32_t (*)[36])(sm + 32 * 72 + 256 * 36);
    float    (*Wqks)[68] = (float (*)[68])(sm + 32 * 72 + 2 * 256 * 36);

    const int tid  = threadIdx.x;
    const int lane = tid & 31;
    const int warp = tid >> 5;
    const int gr   = lane >> 2;   // 0..7
    const int tig  = lane & 3;    // 0..3

    const size_t pos0 = (size_t)blockIdx.x * 64;
    const int b  = (int)(pos0 / HWD);
    const int p0 = (int)(pos0 % HWD);

    // v-mma warp tile: 16 p x 128 o
    const int wp = (warp & 3) * 16;
    const int wo = (warp >> 2) * 128;

    // qk FFMA mapping: 4 o x 4 p per thread
    const int o0q = (tid & 15) * 4;
    const int p0q = (tid >> 4) * 4;

    float c[16][4];
    #pragma unroll
    for (int t = 0; t < 16; t++) {
        const float b0v = bv[wo + t * 8 + 2 * tig];
        const float b1v = bv[wo + t * 8 + 2 * tig + 1];
        c[t][0] = b0v; c[t][1] = b1v; c[t][2] = b0v; c[t][3] = b1v;
    }
    float qacc[4][4];
    {
        float bj[4];
        #pragma unroll
        for (int j = 0; j < 4; j++)
            bj[j] = (o0q < 32) ? bq[o0q + j] : bk[o0q - 32 + j];
        #pragma unroll
        for (int i = 0; i < 4; i++)
            #pragma unroll
            for (int j = 0; j < 4; j++) qacc[i][j] = bj[j];
    }

    const float* Xg = query + (size_t)b * CC * HWD + p0;

    for (int cc0 = 0; cc0 < CC; cc0 += 32) {
        // --- load X chunk [32 k][64 p]: 512 float4 (16 float4 per row) ---
        #pragma unroll
        for (int j = 0; j < 2; j++) {
            const int f  = tid + j * 256;
            const int k  = f >> 4;          // 0..31
            const int p4 = (f & 15) * 4;    // 0..60
            float4 v = *(const float4*)(Xg + (size_t)(cc0 + k) * HWD + p4);
            *(float4*)&Xs[k][p4] = v;
        }
        // --- load Wv hi/lo chunk [256 o][32 k] (2048 uint4 each) ---
        #pragma unroll
        for (int j = 0; j < 8; j++) {
            const int f  = tid + j * 256;
            const int o  = f >> 3;
            const int k4 = (f & 7) * 4;
            *(uint4*)&Wvh[o][k4] = *(const uint4*)&g_wvh[(size_t)o * 256 + cc0 + k4];
            *(uint4*)&Wvl[o][k4] = *(const uint4*)&g_wvl[(size_t)o * 256 + cc0 + k4];
        }
        // --- load Wq/Wk chunk [32 k][64 o] ---
        #pragma unroll
        for (int j = 0; j < 8; j++) {
            const int f = tid + j * 256;
            const int o = f >> 5;
            const int k = f & 31;
            const float w = (o < 32) ? Wq[o * 256 + cc0 + k]
                                     : Wk[(o - 32) * 256 + cc0 + k];
            Wqks[k][o] = w;
        }
        __syncthreads();

        // --- V: 3xTF32 mma over 4 k-steps of 8 ---
        #pragma unroll
        for (int ks = 0; ks < 4; ks++) {
            const int k0 = ks * 8;
            const float x0f = Xs[k0 + tig][wp + gr];
            const float x1f = Xs[k0 + tig][wp + gr + 8];
            const float x2f = Xs[k0 + tig + 4][wp + gr];
            const float x3f = Xs[k0 + tig + 4][wp + gr + 8];
            const uint32_t ah0 = cvt_tf32(x0f), ah1 = cvt_tf32(x1f);
            const uint32_t ah2 = cvt_tf32(x2f), ah3 = cvt_tf32(x3f);
            const uint32_t al0 = cvt_tf32(x0f - __uint_as_float(ah0));
            const uint32_t al1 = cvt_tf32(x1f - __uint_as_float(ah1));
            const uint32_t al2 = cvt_tf32(x2f - __uint_as_float(ah2));
            const uint32_t al3 = cvt_tf32(x3f - __uint_as_float(ah3));
            #pragma unroll
            for (int t = 0; t < 16; t++) {
                const int ob = wo + t * 8;
                const uint32_t bh0 = Wvh[ob + gr][k0 + tig];
                const uint32_t bh1 = Wvh[ob + gr][k0 + tig + 4];
                const uint32_t bl0 = Wvl[ob + gr][k0 + tig];
                const uint32_t bl1 = Wvl[ob + gr][k0 + tig + 4];
                asm volatile(
                    "mma.sync.aligned.m16n8k8.row.col.f32.tf32.tf32.f32 "
                    "{%0,%1,%2,%3}, {%4,%5,%6,%7}, {%8,%9}, {%0,%1,%2,%3};\n"
                    : "+f"(c[t][0]), "+f"(c[t][1]), "+f"(c[t][2]), "+f"(c[t][3])
                    : "r"(ah0), "r"(ah1), "r"(ah2), "r"(ah3), "r"(bh0), "r"(bh1));
                asm volatile(
                    "mma.sync.aligned.m16n8k8.row.col.f32.tf32.tf32.f32 "
                    "{%0,%1,%2,%3}, {%4,%5,%6,%7}, {%8,%9}, {%0,%1,%2,%3};\n"
                    : "+f"(c[t][0]), "+f"(c[t][1]), "+f"(c[t][2]), "+f"(c[t][3])
                    : "r"(ah0), "r"(ah1), "r"(ah2), "r"(ah3), "r"(bl0), "r"(bl1));
                asm volatile(
                    "mma.sync.aligned.m16n8k8.row.col.f32.tf32.tf32.f32 "
                    "{%0,%1,%2,%3}, {%4,%5,%6,%7}, {%8,%9}, {%0,%1,%2,%3};\n"
                    : "+f"(c[t][0]), "+f"(c[t][1]), "+f"(c[t][2]), "+f"(c[t][3])
                    : "r"(al0), "r"(al1), "r"(al2), "r"(al3), "r"(bh0), "r"(bh1));
            }
        }

        // --- Q/K: fp32 FFMA ---
        #pragma unroll 4
        for (int k = 0; k < 32; k++) {
            const float4 w = *(const float4*)&Wqks[k][o0q];
            const float4 x = *(const float4*)&Xs[k][p0q];
            const float xi[4] = {x.x, x.y, x.z, x.w};
            #pragma unroll
            for (int i = 0; i < 4; i++) {
                qacc[i][0] += xi[i] * w.x;
                qacc[i][1] += xi[i] * w.y;
                qacc[i][2] += xi[i] * w.z;
                qacc[i][3] += xi[i] * w.w;
            }
        }
        __syncthreads();
    }

    // --- store V ---
    #pragma unroll
    for (int t = 0; t < 16; t++) {
        const int o = wo + t * 8 + 2 * tig;
        const size_t pa = pos0 + wp + gr;
        *(float2*)&g_v[pa * CC + o]       = make_float2(c[t][0], c[t][1]);
        *(float2*)&g_v[(pa + 8) * CC + o] = make_float2(c[t][2], c[t][3]);
    }
    // --- store Q/K ---
    #pragma unroll
    for (int i = 0; i < 4; i++) {
        const size_t pp = pos0 + p0q + i;
        const float4 r = make_float4(qacc[i][0], qacc[i][1], qacc[i][2], qacc[i][3]);
        if (o0q < 32) *(float4*)&g_q[pp * EE + o0q]        = r;
        else          *(float4*)&g_k[pp * EE + (o0q - 32)] = r;
    }
}

// ---------------------------------------------------------------------------
// Kernel 2: raw logits per axis (q.k over 48-line), eH diagonal masked.
// ---------------------------------------------------------------------------
__global__ __launch_bounds__(256) void logits_kernel()
{
    const int l    = blockIdx.x;
    const int axis = blockIdx.y;
    const int b    = blockIdx.z;
    const int tid  = threadIdx.x;

    __shared__ float Qs[48][32];
    __shared__ float Ks[48][32];

    const int a1 = l / 48, a2 = l % 48;
    int base, stride;
    if      (axis == 0) { base = a1 * 48 + a2;      stride = WD; }
    else if (axis == 1) { base = a1 * WD + a2;      stride = 48; }
    else                { base = a1 * WD + a2 * 48; stride = 1;  }

    const size_t b0 = (size_t)b * HWD;

    for (int f = tid; f < 48 * 32; f += 256) {
        const int y = f >> 5, e = f & 31;
        const size_t p = b0 + base + (size_t)y * stride;
        Qs[y][e] = g_q[p * EE + e];
        Ks[y][e] = g_k[p * EE + e];
    }
    __syncthreads();

    #pragma unroll
    for (int k = 0; k < 9; k++) {
        const int id = tid + k * 256;
        const int x = id / 48, y = id % 48;
        float s = 0.f;
        #pragma unroll
        for (int e = 0; e < 32; e++) s += Qs[x][e] * Ks[y][e];
        if (axis == 0 && x == y) s = -3.0e38f;
        const size_t p = b0 + base + (size_t)x * stride;
        g_att[p * NL + axis * 48 + y] = s;
    }
}

// ---------------------------------------------------------------------------
// Kernel 3: per-position softmax stats (max, 1/sum) over 144 logits.
// ---------------------------------------------------------------------------
__global__ __launch_bounds__(256) void mz_kernel()
{
    const int tid  = threadIdx.x;
    const int pos  = blockIdx.x * 32 + (tid >> 3);
    const int lane = tid & 7;
    const float* row = g_att + (size_t)pos * NL;

    float4 v[5];
    float m = -3.4e38f;
    #pragma unroll
    for (int k = 0; k < 5; k++) {
        const int j = lane + k * 8;
        if (j < 36) {
            v[k] = *(const float4*)&row[j * 4];
            m = fmaxf(m, fmaxf(fmaxf(v[k].x, v[k].y), fmaxf(v[k].z, v[k].w)));
        }
    }
    #pragma unroll
    for (int o = 1; o < 8; o <<= 1)
        m = fmaxf(m, __shfl_xor_sync(0xffffffffu, m, o));

    float s = 0.f;
    #pragma unroll
    for (int k = 0; k < 5; k++) {
        const int j = lane + k * 8;
        if (j < 36) {
            s += expf(v[k].x - m) + expf(v[k].y - m)
               + expf(v[k].z - m) + expf(v[k].w - m);
        }
    }
    #pragma unroll
    for (int o = 1; o < 8; o <<= 1)
        s += __shfl_xor_sync(0xffffffffu, s, o);

    if (lane == 0) g_mz[pos] = make_float2(m, 1.f / s);
}

// ---------------------------------------------------------------------------
// Kernel 4/5/6: aggregation per axis (normalizes logits on the fly).
//   out_line[x][c] = sum_y softmax(A)[x][y] * V[y][c]
// AXIS 0 writes g_acc, AXIS 1 RMWs, AXIS 2 fuses final epilogue.
// 512 threads: 16 x-groups (3 x each) x 32 c-lanes.
// ---------------------------------------------------------------------------
template<int AXIS>
__global__ __launch_bounds__(512) void agg_kernel(
    const float* __restrict__ query,
    const float* __restrict__ gamma,
    float* __restrict__ out)
{
    extern __shared__ float sm[];
    float  (*Vs)[256] = (float (*)[256])sm;              // 48x256
    float  (*As)[48]  = (float (*)[48])(sm + 48 * 256);  // 48x48
    float2* mzs       = (float2*)(sm + 48 * 256 + 48 * 48);

    const int l   = blockIdx.x;
    const int b   = blockIdx.y;
    const int tid = threadIdx.x;

    const int a1 = l / 48, a2 = l % 48;
    int base, stride;
    if      (AXIS == 0) { base = a1 * 48 + a2;      stride = WD; }
    else if (AXIS == 1) { base = a1 * WD + a2;      stride = 48; }
    else                { base = a1 * WD + a2 * 48; stride = 1;  }

    const size_t b0 = (size_t)b * HWD;

    if (tid < 48) mzs[tid] = g_mz[b0 + base + (size_t)tid * stride];

    // load V line (48 x 256), 3072 float4
    #pragma unroll
    for (int k = 0; k < 6; k++) {
        const int f  = tid + k * 512;
        const int y  = f >> 6;
        const int c4 = f & 63;
        *(float4*)&Vs[y][c4 * 4] =
            *(const float4*)&g_v[(b0 + base + (size_t)y * stride) * CC + c4 * 4];
    }
    __syncthreads();

    // load + normalize A (48 x 48)
    for (int f = tid; f < 48 * 48; f += 512) {
        const int x = f / 48, y = f % 48;
        const float raw = g_att[(b0 + base + (size_t)x * stride) * NL + AXIS * 48 + y];
        const float2 mz = mzs[x];
        As[x][y] = expf(raw - mz.x) * mz.y;
    }
    __syncthreads();

    const int cg = tid & 31;
    const int ca = cg * 4;
    const int xg = tid >> 5;
    const int x0 = xg * 3;

    float acc[3][8];
    #pragma unroll
    for (int i = 0; i < 3; i++)
        #pragma unroll
        for (int j = 0; j < 8; j++) acc[i][j] = 0.f;

    #pragma unroll 2
    for (int y = 0; y < 48; y++) {
        const float4 v0 = *(const float4*)&Vs[y][ca];
        const float4 v1 = *(const float4*)&Vs[y][ca + 128];
        #pragma unroll
        for (int xi = 0; xi < 3; xi++) {
            const float a = As[x0 + xi][y];
            acc[xi][0] += a * v0.x; acc[xi][1] += a * v0.y;
            acc[xi][2] += a * v0.z; acc[xi][3] += a * v0.w;
            acc[xi][4] += a * v1.x; acc[xi][5] += a * v1.y;
            acc[xi][6] += a * v1.z; acc[xi][7] += a * v1.w;
        }
    }

    if (AXIS == 0) {
        #pragma unroll
        for (int xi = 0; xi < 3; xi++) {
            const size_t p = b0 + base + (size_t)(x0 + xi) * stride;
            *(float4*)&g_acc[p * CC + ca]       = make_float4(acc[xi][0], acc[xi][1], acc[xi][2], acc[xi][3]);
            *(float4*)&g_acc[p * CC + ca + 128] = make_float4(acc[xi][4], acc[xi][5], acc[xi][6], acc[xi][7]);
        }
    } else if (AXIS == 1) {
        #pragma unroll
        for (int xi = 0; xi < 3; xi++) {
            const size_t p = b0 + base + (size_t)(x0 + xi) * stride;
            float4 a0 = *(const float4*)&g_acc[p * CC + ca];
            float4 a1 = *(const float4*)&g_acc[p * CC + ca + 128];
            a0.x += acc[xi][0]; a0.y += acc[xi][1]; a0.z += acc[xi][2]; a0.w += acc[xi][3];
            a1.x += acc[xi][4]; a1.y += acc[xi][5]; a1.z += acc[xi][6]; a1.w += acc[xi][7];
            *(float4*)&g_acc[p * CC + ca]       = a0;
            *(float4*)&g_acc[p * CC + ca + 128] = a1;
        }
    } else {
        __syncthreads();
        float (*Rs)[256] = Vs;
        #pragma unroll
        for (int xi = 0; xi < 3; xi++) {
            const int x = x0 + xi;
            const size_t p = b0 + base + x;     // stride 1
            const float4 a0 = *(const float4*)&g_acc[p * CC + ca];
            const float4 a1 = *(const float4*)&g_acc[p * CC + ca + 128];
            *(float4*)&Rs[x][ca] = make_float4(acc[xi][0] + a0.x, acc[xi][1] + a0.y,
                                               acc[xi][2] + a0.z, acc[xi][3] + a0.w);
            *(float4*)&Rs[x][ca + 128] = make_float4(acc[xi][4] + a1.x, acc[xi][5] + a1.y,
                                                     acc[xi][6] + a1.z, acc[xi][7] + a1.w);
        }
        __syncthreads();

        const float gm = gamma[0];
        const int c  = tid & 255;
        const int xh = tid >> 8;
        const size_t gidx = ((size_t)b * CC + c) * HWD + base;
        #pragma unroll 4
        for (int x = xh * 24; x < xh * 24 + 24; x++) {
            out[gidx + x] = gm * Rs[x][c] + query[gidx + x];
        }
    }
}

// ---------------------------------------------------------------------------
extern "C" void kernel_launch(void* const* d_in, const int* in_sizes, int n_in,
                              void* d_out, int out_size)
{
    const float* query = (const float*)d_in[0];
    const float* Wq    = (const float*)d_in[1];
    const float* bq    = (const float*)d_in[2];
    const float* Wk    = (const float*)d_in[3];
    const float* bk    = (const float*)d_in[4];
    const float* Wv    = (const float*)d_in[5];
    const float* bv    = (const float*)d_in[6];
    const float* gamma = (const float*)d_in[7];
    float* out = (float*)d_out;

    const int PROJ_SMEM = (32 * 72 + 2 * 256 * 36 + 32 * 68) * 4;      // 91648
    const int AGG_SMEM  = (48 * 256 + 48 * 48) * 4 + 48 * 8;           // 58752

    cudaFuncSetAttribute(proj_kernel,   cudaFuncAttributeMaxDynamicSharedMemorySize, PROJ_SMEM);
    cudaFuncSetAttribute(agg_kernel<0>, cudaFuncAttributeMaxDynamicSharedMemorySize, AGG_SMEM);
    cudaFuncSetAttribute(agg_kernel<1>, cudaFuncAttributeMaxDynamicSharedMemorySize, AGG_SMEM);
    cudaFuncSetAttribute(agg_kernel<2>, cudaFuncAttributeMaxDynamicSharedMemorySize, AGG_SMEM);

    wv_split_kernel<<<256, 256>>>(Wv);
    proj_kernel    <<<NP / 64, 256, PROJ_SMEM>>>(query, Wq, bq, Wk, bk, bv);
    logits_kernel  <<<dim3(WD, 3, BB), 256>>>();
    mz_kernel      <<<NP / 32, 256>>>();
    agg_kernel<0>  <<<dim3(WD, BB), 512, AGG_SMEM>>>(query, gamma, out);
    agg_kernel<1>  <<<dim3(WD, BB), 512, AGG_SMEM>>>(query, gamma, out);
    agg_kernel<2>  <<<dim3(WD, BB), 512, AGG_SMEM>>>(query, gamma, out);
}

// round 5
// speedup vs baseline: 1.3377x; 1.1564x over previous
#include <cuda_runtime.h>
#include <cuda_bf16.h>
#include <math.h>
#include <stdint.h>

// Problem constants
#define BB   2
#define CC   256
#define EE   32
#define WD   2304      // W*D
#define HWD  110592    // H*W*D
#define NP   221184    // B*HWD
#define NL   144       // 3*48 logits per position

// ---------------------------------------------------------------------------
// Scratch (device globals: allocation-free rule)
// ---------------------------------------------------------------------------
__device__ float         g_q  [(size_t)NP * EE];
__device__ float         g_k  [(size_t)NP * EE];
__device__ float         g_v  [(size_t)NP * CC];
__device__ float         g_att[(size_t)NP * NL];
__device__ float2        g_mz [(size_t)NP];
__device__ float         g_acc[(size_t)NP * CC];
// W rows: 0..255 = Wv, 256..287 = Wq, 288..319 = Wk  (bf16 hi/lo split)
__device__ __nv_bfloat16 g_wh [320 * 256];
__device__ __nv_bfloat16 g_wl [320 * 256];

__device__ __forceinline__ uint32_t smem_u32(const void* p) {
    uint32_t a;
    asm("{ .reg .u64 t; cvta.to.shared.u64 t, %1; cvt.u32.u64 %0, t; }"
        : "=r"(a) : "l"(p));
    return a;
}

__device__ __forceinline__ uint32_t pack_bf2(__nv_bfloat16 a, __nv_bfloat16 b) {
    return (uint32_t)__bfloat16_as_ushort(a)
         | ((uint32_t)__bfloat16_as_ushort(b) << 16);
}

#define LDSM_T(r, addr) \
    asm volatile("ldmatrix.sync.aligned.m8n8.x4.trans.shared.b16 {%0,%1,%2,%3}, [%4];" \
                 : "=r"((r)[0]), "=r"((r)[1]), "=r"((r)[2]), "=r"((r)[3]) : "r"(addr))
#define LDSM_N(r, addr) \
    asm volatile("ldmatrix.sync.aligned.m8n8.x4.shared.b16 {%0,%1,%2,%3}, [%4];" \
                 : "=r"((r)[0]), "=r"((r)[1]), "=r"((r)[2]), "=r"((r)[3]) : "r"(addr))
#define MMA_BF16(c, a, b0, b1) \
    asm volatile("mma.sync.aligned.m16n8k16.row.col.f32.bf16.bf16.f32 " \
                 "{%0,%1,%2,%3}, {%4,%5,%6,%7}, {%8,%9}, {%0,%1,%2,%3};" \
                 : "+f"((c)[0]), "+f"((c)[1]), "+f"((c)[2]), "+f"((c)[3]) \
                 : "r"((a)[0]), "r"((a)[1]), "r"((a)[2]), "r"((a)[3]), \
                   "r"(b0), "r"(b1))
#define CP16(dst, src) \
    asm volatile("cp.async.cg.shared.global [%0], [%1], 16;" :: "r"(dst), "l"(src))
#define CP_COMMIT() asm volatile("cp.async.commit_group;")
#define CP_WAIT0()  asm volatile("cp.async.wait_group 0;" ::: "memory")

// ---------------------------------------------------------------------------
// Kernel 0: split W into bf16 hi/lo
// ---------------------------------------------------------------------------
__global__ __launch_bounds__(256) void w_split_kernel(
    const float* __restrict__ Wq, const float* __restrict__ Wk,
    const float* __restrict__ Wv)
{
    const int r = blockIdx.x;
    const int c = threadIdx.x;
    const float w = (r < 256) ? Wv[r * 256 + c]
                  : (r < 288) ? Wq[(r - 256) * 256 + c]
                              : Wk[(r - 288) * 256 + c];
    const __nv_bfloat16 h = __float2bfloat16(w);
    const __nv_bfloat16 l = __float2bfloat16(w - __bfloat162float(h));
    g_wh[r * 256 + c] = h;
    g_wl[r * 256 + c] = l;
}

// ---------------------------------------------------------------------------
// Projection GEMM via mma.sync bf16 (3-term hi/lo split, fp32 accumulate).
//   D[p][o] = sum_k X[k][p] * W[o][k] + bias[o]
// CTA tile: 128 positions x NROWS outputs, K = 256 in 8 stages of 32.
// A (X) staged [k][136p] bf16 hi/lo  -> ldmatrix.x4.trans
// B (W) staged [o][40k]  bf16 hi/lo  -> ldmatrix.x4 (via cp.async)
// Warps: 4(m) x 2(n); warp tile 32p x NROWS/2 o.
// NROWS = 128 (V tiles, grid (2, 1728)) or 64 (QK, grid 1728).
// ---------------------------------------------------------------------------
template<int NROWS>
__global__ __launch_bounds__(256, 1) void proj_mma_kernel(
    const float* __restrict__ query,
    const float* __restrict__ bq, const float* __restrict__ bk,
    const float* __restrict__ bv)
{
    constexpr int NT   = NROWS / 16;       // n-tiles per warp (8 or 4)
    constexpr int WN   = NROWS / 2;        // warp n extent (64 or 32)
    constexpr int ABUF = 32 * 136 * 2;     // 8704 B
    constexpr int BBUF = NROWS * 40 * 2;   // 10240 or 5120 B

    extern __shared__ char sm[];
    const uint32_t A_H = smem_u32(sm);
    const uint32_t A_L = A_H + 2 * ABUF;
    const uint32_t B_H = A_H + 4 * ABUF;
    const uint32_t B_L = B_H + 2 * BBUF;

    const int tid  = threadIdx.x;
    const int lane = tid & 31;
    const int warp = tid >> 5;
    const int wm   = warp & 3;             // m (position) warp index
    const int wn   = warp >> 2;            // n (output) warp index
    const int g    = lane >> 2;
    const int tg   = lane & 3;

    const int ob = (NROWS == 128) ? (int)blockIdx.x * 128 : 256;  // W row base
    const int pt = (NROWS == 128) ? (int)blockIdx.y : (int)blockIdx.x;

    const size_t pos0 = (size_t)pt * 128;
    const int b  = (int)(pos0 / HWD);
    const int p0 = (int)(pos0 % HWD);
    const float* Xb = query + (size_t)b * CC * HWD + p0;

    // ldmatrix lane offsets
    const int aRowL = ((lane >> 4) << 3) + (lane & 7);   // k offset in 16-block
    const int aColL = ((lane >> 3) & 1) * 8;             // p offset
    const int bRowL = aRowL;                              // n offset in 16-group
    const int bColL = aColL;                              // k offset

    float acc[2][NT][4];
    #pragma unroll
    for (int mt = 0; mt < 2; mt++)
        #pragma unroll
        for (int nt = 0; nt < NT; nt++)
            #pragma unroll
            for (int i = 0; i < 4; i++) acc[mt][nt][i] = 0.f;

    float4 xa[4];

    // ---- helpers as lambdas ----
    auto ldga = [&](int t) {
        const int k0 = t * 32;
        #pragma unroll
        for (int j = 0; j < 4; j++) {
            const int f  = tid + j * 256;
            const int kr = f >> 5;
            const int p4 = (f & 31) * 4;
            xa[j] = *(const float4*)(Xb + (size_t)(k0 + kr) * HWD + p4);
        }
    };
    auto stsa = [&](int buf) {
        #pragma unroll
        for (int j = 0; j < 4; j++) {
            const int f  = tid + j * 256;
            const int kr = f >> 5;
            const int p4 = (f & 31) * 4;
            const float xs[4] = {xa[j].x, xa[j].y, xa[j].z, xa[j].w};
            __nv_bfloat16 h[4], l[4];
            #pragma unroll
            for (int e = 0; e < 4; e++) {
                h[e] = __float2bfloat16(xs[e]);
                l[e] = __float2bfloat16(xs[e] - __bfloat162float(h[e]));
            }
            const uint32_t off = (uint32_t)(kr * 136 + p4) * 2;
            *(uint2*)(uintptr_t)0; // placeholder avoided
            uint32_t dh = A_H + buf * ABUF + off;
            uint32_t dl = A_L + buf * ABUF + off;
            uint2 vh = make_uint2(pack_bf2(h[0], h[1]), pack_bf2(h[2], h[3]));
            uint2 vl = make_uint2(pack_bf2(l[0], l[1]), pack_bf2(l[2], l[3]));
            asm volatile("st.shared.v2.u32 [%0], {%1,%2};" :: "r"(dh), "r"(vh.x), "r"(vh.y));
            asm volatile("st.shared.v2.u32 [%0], {%1,%2};" :: "r"(dl), "r"(vl.x), "r"(vl.y));
        }
    };
    auto cpb = [&](int t, int buf) {
        const int k0 = t * 32;
        constexpr int CH = NROWS * 4;      // 16B chunks for hi
        #pragma unroll
        for (int j = 0; j < CH / 256; j++) {
            const int id  = tid + j * 256;
            const int row = id >> 2;
            const int seg = id & 3;
            const uint32_t doff = (uint32_t)(row * 40 + seg * 8) * 2;
            CP16(B_H + buf * BBUF + doff, &g_wh[(size_t)(ob + row) * 256 + k0 + seg * 8]);
            CP16(B_L + buf * BBUF + doff, &g_wl[(size_t)(ob + row) * 256 + k0 + seg * 8]);
        }
    };
    auto compute = [&](int buf) {
        #pragma unroll
        for (int k16 = 0; k16 < 32; k16 += 16) {
            uint32_t ah[2][4], al[2][4];
            #pragma unroll
            for (int mt = 0; mt < 2; mt++) {
                const uint32_t off =
                    (uint32_t)((k16 + aRowL) * 136 + wm * 32 + mt * 16 + aColL) * 2;
                LDSM_T(ah[mt], A_H + buf * ABUF + off);
                LDSM_T(al[mt], A_L + buf * ABUF + off);
            }
            uint32_t bh[NT / 2][4], bl[NT / 2][4];
            #pragma unroll
            for (int np = 0; np < NT / 2; np++) {
                const uint32_t off =
                    (uint32_t)((wn * WN + np * 16 + bRowL) * 40 + k16 + bColL) * 2;
                LDSM_N(bh[np], B_H + buf * BBUF + off);
                LDSM_N(bl[np], B_L + buf * BBUF + off);
            }
            #pragma unroll
            for (int mt = 0; mt < 2; mt++)
                #pragma unroll
                for (int np = 0; np < NT / 2; np++)
                    #pragma unroll
                    for (int h = 0; h < 2; h++) {
                        const int nt = np * 2 + h;
                        MMA_BF16(acc[mt][nt], ah[mt], bh[np][h*2], bh[np][h*2+1]);
                        MMA_BF16(acc[mt][nt], ah[mt], bl[np][h*2], bl[np][h*2+1]);
                        MMA_BF16(acc[mt][nt], al[mt], bh[np][h*2], bh[np][h*2+1]);
                    }
        }
    };

    // ---- pipeline ----
    ldga(0);
    cpb(0, 0);
    CP_COMMIT();
    stsa(0);
    CP_WAIT0();
    __syncthreads();

    #pragma unroll 1
    for (int t = 0; t < 8; t++) {
        if (t < 7) {
            ldga(t + 1);
            cpb(t + 1, (t + 1) & 1);
            CP_COMMIT();
        }
        compute(t & 1);
        if (t < 7) stsa((t + 1) & 1);
        CP_WAIT0();
        __syncthreads();
    }

    // ---- epilogue ----
    #pragma unroll
    for (int mt = 0; mt < 2; mt++) {
        const size_t prow = pos0 + wm * 32 + mt * 16 + g;
        #pragma unroll
        for (int nt = 0; nt < NT; nt++) {
            const int n = wn * WN + nt * 8 + tg * 2;
            if (NROWS == 128) {
                const int oc = (int)blockIdx.x * 128 + n;
                const float b0 = bv[oc], b1 = bv[oc + 1];
                *(float2*)&g_v[prow * CC + oc] =
                    make_float2(acc[mt][nt][0] + b0, acc[mt][nt][1] + b1);
                *(float2*)&g_v[(prow + 8) * CC + oc] =
                    make_float2(acc[mt][nt][2] + b0, acc[mt][nt][3] + b1);
            } else {
                if (n < 32) {
                    const float b0 = bq[n], b1 = bq[n + 1];
                    *(float2*)&g_q[prow * EE + n] =
                        make_float2(acc[mt][nt][0] + b0, acc[mt][nt][1] + b1);
                    *(float2*)&g_q[(prow + 8) * EE + n] =
                        make_float2(acc[mt][nt][2] + b0, acc[mt][nt][3] + b1);
                } else {
                    const float b0 = bk[n - 32], b1 = bk[n - 31];
                    *(float2*)&g_k[prow * EE + n - 32] =
                        make_float2(acc[mt][nt][0] + b0, acc[mt][nt][1] + b1);
                    *(float2*)&g_k[(prow + 8) * EE + n - 32] =
                        make_float2(acc[mt][nt][2] + b0, acc[mt][nt][3] + b1);
                }
            }
        }
    }
}

// ---------------------------------------------------------------------------
// Kernel 2: raw logits per axis (q.k over 48-line), eH diagonal masked.
// ---------------------------------------------------------------------------
__global__ __launch_bounds__(256) void logits_kernel()
{
    const int l    = blockIdx.x;
    const int axis = blockIdx.y;
    const int b    = blockIdx.z;
    const int tid  = threadIdx.x;

    __shared__ float Qs[48][32];
    __shared__ float Ks[48][32];

    const int a1 = l / 48, a2 = l % 48;
    int base, stride;
    if      (axis == 0) { base = a1 * 48 + a2;      stride = WD; }
    else if (axis == 1) { base = a1 * WD + a2;      stride = 48; }
    else                { base = a1 * WD + a2 * 48; stride = 1;  }

    const size_t b0 = (size_t)b * HWD;

    for (int f = tid; f < 48 * 32; f += 256) {
        const int y = f >> 5, e = f & 31;
        const size_t p = b0 + base + (size_t)y * stride;
        Qs[y][e] = g_q[p * EE + e];
        Ks[y][e] = g_k[p * EE + e];
    }
    __syncthreads();

    #pragma unroll
    for (int k = 0; k < 9; k++) {
        const int id = tid + k * 256;
        const int x = id / 48, y = id % 48;
        float s = 0.f;
        #pragma unroll
        for (int e = 0; e < 32; e++) s += Qs[x][e] * Ks[y][e];
        if (axis == 0 && x == y) s = -3.0e38f;
        const size_t p = b0 + base + (size_t)x * stride;
        g_att[p * NL + axis * 48 + y] = s;
    }
}

// ---------------------------------------------------------------------------
// Kernel 3: per-position softmax stats (max, 1/sum) over 144 logits.
// ---------------------------------------------------------------------------
__global__ __launch_bounds__(256) void mz_kernel()
{
    const int tid  = threadIdx.x;
    const int pos  = blockIdx.x * 32 + (tid >> 3);
    const int lane = tid & 7;
    const float* row = g_att + (size_t)pos * NL;

    float4 v[5];
    float m = -3.4e38f;
    #pragma unroll
    for (int k = 0; k < 5; k++) {
        const int j = lane + k * 8;
        if (j < 36) {
            v[k] = *(const float4*)&row[j * 4];
            m = fmaxf(m, fmaxf(fmaxf(v[k].x, v[k].y), fmaxf(v[k].z, v[k].w)));
        }
    }
    #pragma unroll
    for (int o = 1; o < 8; o <<= 1)
        m = fmaxf(m, __shfl_xor_sync(0xffffffffu, m, o));

    float s = 0.f;
    #pragma unroll
    for (int k = 0; k < 5; k++) {
        const int j = lane + k * 8;
        if (j < 36) {
            s += expf(v[k].x - m) + expf(v[k].y - m)
               + expf(v[k].z - m) + expf(v[k].w - m);
        }
    }
    #pragma unroll
    for (int o = 1; o < 8; o <<= 1)
        s += __shfl_xor_sync(0xffffffffu, s, o);

    if (lane == 0) g_mz[pos] = make_float2(m, 1.f / s);
}

// ---------------------------------------------------------------------------
// Kernel 4/5/6: aggregation per axis (normalizes logits on the fly).
// ---------------------------------------------------------------------------
template<int AXIS>
__global__ __launch_bounds__(512) void agg_kernel(
    const float* __restrict__ query,
    const float* __restrict__ gamma,
    float* __restrict__ out)
{
    extern __shared__ float smf[];
    float  (*Vs)[256] = (float (*)[256])smf;              // 48x256
    float  (*As)[48]  = (float (*)[48])(smf + 48 * 256);  // 48x48
    float2* mzs       = (float2*)(smf + 48 * 256 + 48 * 48);

    const int l   = blockIdx.x;
    const int b   = blockIdx.y;
    const int tid = threadIdx.x;

    const int a1 = l / 48, a2 = l % 48;
    int base, stride;
    if      (AXIS == 0) { base = a1 * 48 + a2;      stride = WD; }
    else if (AXIS == 1) { base = a1 * WD + a2;      stride = 48; }
    else                { base = a1 * WD + a2 * 48; stride = 1;  }

    const size_t b0 = (size_t)b * HWD;

    if (tid < 48) mzs[tid] = g_mz[b0 + base + (size_t)tid * stride];

    #pragma unroll
    for (int k = 0; k < 6; k++) {
        const int f  = tid + k * 512;
        const int y  = f >> 6;
        const int c4 = f & 63;
        *(float4*)&Vs[y][c4 * 4] =
            *(const float4*)&g_v[(b0 + base + (size_t)y * stride) * CC + c4 * 4];
    }
    __syncthreads();

    for (int f = tid; f < 48 * 48; f += 512) {
        const int x = f / 48, y = f % 48;
        const float raw = g_att[(b0 + base + (size_t)x * stride) * NL + AXIS * 48 + y];
        const float2 mz = mzs[x];
        As[x][y] = expf(raw - mz.x) * mz.y;
    }
    __syncthreads();

    const int cg = tid & 31;
    const int ca = cg * 4;
    const int xg = tid >> 5;
    const int x0 = xg * 3;

    float acc[3][8];
    #pragma unroll
    for (int i = 0; i < 3; i++)
        #pragma unroll
        for (int j = 0; j < 8; j++) acc[i][j] = 0.f;

    #pragma unroll 2
    for (int y = 0; y < 48; y++) {
        const float4 v0 = *(const float4*)&Vs[y][ca];
        const float4 v1 = *(const float4*)&Vs[y][ca + 128];
        #pragma unroll
        for (int xi = 0; xi < 3; xi++) {
            const float a = As[x0 + xi][y];
            acc[xi][0] += a * v0.x; acc[xi][1] += a * v0.y;
            acc[xi][2] += a * v0.z; acc[xi][3] += a * v0.w;
            acc[xi][4] += a * v1.x; acc[xi][5] += a * v1.y;
            acc[xi][6] += a * v1.z; acc[xi][7] += a * v1.w;
        }
    }

    if (AXIS == 0) {
        #pragma unroll
        for (int xi = 0; xi < 3; xi++) {
            const size_t p = b0 + base + (size_t)(x0 + xi) * stride;
            *(float4*)&g_acc[p * CC + ca]       = make_float4(acc[xi][0], acc[xi][1], acc[xi][2], acc[xi][3]);
            *(float4*)&g_acc[p * CC + ca + 128] = make_float4(acc[xi][4], acc[xi][5], acc[xi][6], acc[xi][7]);
        }
    } else if (AXIS == 1) {
        #pragma unroll
        for (int xi = 0; xi < 3; xi++) {
            const size_t p = b0 + base + (size_t)(x0 + xi) * stride;
            float4 a0 = *(const float4*)&g_acc[p * CC + ca];
            float4 a1 = *(const float4*)&g_acc[p * CC + ca + 128];
            a0.x += acc[xi][0]; a0.y += acc[xi][1]; a0.z += acc[xi][2]; a0.w += acc[xi][3];
            a1.x += acc[xi][4]; a1.y += acc[xi][5]; a1.z += acc[xi][6]; a1.w += acc[xi][7];
            *(float4*)&g_acc[p * CC + ca]       = a0;
            *(float4*)&g_acc[p * CC + ca + 128] = a1;
        }
    } else {
        __syncthreads();
        float (*Rs)[256] = Vs;
        #pragma unroll
        for (int xi = 0; xi < 3; xi++) {
            const int x = x0 + xi;
            const size_t p = b0 + base + x;     // stride 1
            const float4 a0 = *(const float4*)&g_acc[p * CC + ca];
            const float4 a1 = *(const float4*)&g_acc[p * CC + ca + 128];
            *(float4*)&Rs[x][ca] = make_float4(acc[xi][0] + a0.x, acc[xi][1] + a0.y,
                                               acc[xi][2] + a0.z, acc[xi][3] + a0.w);
            *(float4*)&Rs[x][ca + 128] = make_float4(acc[xi][4] + a1.x, acc[xi][5] + a1.y,
                                                     acc[xi][6] + a1.z, acc[xi][7] + a1.w);
        }
        __syncthreads();

        const float gm = gamma[0];
        const int c  = tid & 255;
        const int xh = tid >> 8;
        const size_t gidx = ((size_t)b * CC + c) * HWD + base;
        #pragma unroll 4
        for (int x = xh * 24; x < xh * 24 + 24; x++) {
            out[gidx + x] = gm * Rs[x][c] + query[gidx + x];
        }
    }
}

// ---------------------------------------------------------------------------
extern "C" void kernel_launch(void* const* d_in, const int* in_sizes, int n_in,
                              void* d_out, int out_size)
{
    const float* query = (const float*)d_in[0];
    const float* Wq    = (const float*)d_in[1];
    const float* bq    = (const float*)d_in[2];
    const float* Wk    = (const float*)d_in[3];
    const float* bk    = (const float*)d_in[4];
    const float* Wv    = (const float*)d_in[5];
    const float* bv    = (const float*)d_in[6];
    const float* gamma = (const float*)d_in[7];
    float* out = (float*)d_out;
    (void)in_sizes; (void)n_in; (void)out_size;

    const int SMEM_V  = 4 * 8704 + 4 * (128 * 40 * 2);  // 34816 + 40960 = 75776
    const int SMEM_QK = 4 * 8704 + 4 * (64 * 40 * 2);   // 34816 + 20480 = 55296
    const int AGG_SMEM = (48 * 256 + 48 * 48) * 4 + 48 * 8;   // 58752

    cudaFuncSetAttribute(proj_mma_kernel<128>, cudaFuncAttributeMaxDynamicSharedMemorySize, SMEM_V);
    cudaFuncSetAttribute(proj_mma_kernel<64>,  cudaFuncAttributeMaxDynamicSharedMemorySize, SMEM_QK);
    cudaFuncSetAttribute(agg_kernel<0>, cudaFuncAttributeMaxDynamicSharedMemorySize, AGG_SMEM);
    cudaFuncSetAttribute(agg_kernel<1>, cudaFuncAttributeMaxDynamicSharedMemorySize, AGG_SMEM);
    cudaFuncSetAttribute(agg_kernel<2>, cudaFuncAttributeMaxDynamicSharedMemorySize, AGG_SMEM);

    w_split_kernel<<<320, 256>>>(Wq, Wk, Wv);
    proj_mma_kernel<128><<<dim3(2, NP / 128), 256, SMEM_V>>>(query, bq, bk, bv);
    proj_mma_kernel<64> <<<NP / 128, 256, SMEM_QK>>>(query, bq, bk, bv);
    logits_kernel <<<dim3(WD, 3, BB), 256>>>();
    mz_kernel     <<<NP / 32, 256>>>();
    agg_kernel<0> <<<dim3(WD, BB), 512, AGG_SMEM>>>(query, gamma, out);
    agg_kernel<1> <<<dim3(WD, BB), 512, AGG_SMEM>>>(query, gamma, out);
    agg_kernel<2> <<<dim3(WD, BB), 512, AGG_SMEM>>>(query, gamma, out);
}

// round 6
// speedup vs baseline: 1.9931x; 1.4899x over previous
#include <cuda_runtime.h>
#include <cuda_bf16.h>
#include <math.h>
#include <stdint.h>

// Problem constants
#define BB   2
#define CC   256
#define EE   32
#define WD   2304      // W*D
#define HWD  110592    // H*W*D
#define NP   221184    // B*HWD
#define NL   144       // 3*48 logits per position

// ---------------------------------------------------------------------------
// Scratch (device globals: allocation-free rule)
// ---------------------------------------------------------------------------
__device__ float         g_q  [(size_t)NP * EE];
__device__ float         g_k  [(size_t)NP * EE];
__device__ float         g_v  [(size_t)NP * CC];
__device__ float         g_att[(size_t)NP * NL];
__device__ float2        g_mz [(size_t)NP];
__device__ float         g_acc[(size_t)NP * CC];
// W rows: 0..255 = Wv, 256..287 = Wq, 288..319 = Wk  (bf16 hi/lo split)
__device__ __nv_bfloat16 g_wh [320 * 256];
__device__ __nv_bfloat16 g_wl [320 * 256];

__device__ __forceinline__ uint32_t smem_u32(const void* p) {
    uint32_t a;
    asm("{ .reg .u64 t; cvta.to.shared.u64 t, %1; cvt.u32.u64 %0, t; }"
        : "=r"(a) : "l"(p));
    return a;
}

__device__ __forceinline__ uint32_t pack_bf2(__nv_bfloat16 a, __nv_bfloat16 b) {
    return (uint32_t)__bfloat16_as_ushort(a)
         | ((uint32_t)__bfloat16_as_ushort(b) << 16);
}

#define LDSM_T(r, addr) \
    asm volatile("ldmatrix.sync.aligned.m8n8.x4.trans.shared.b16 {%0,%1,%2,%3}, [%4];" \
                 : "=r"((r)[0]), "=r"((r)[1]), "=r"((r)[2]), "=r"((r)[3]) : "r"(addr))
#define LDSM_N(r, addr) \
    asm volatile("ldmatrix.sync.aligned.m8n8.x4.shared.b16 {%0,%1,%2,%3}, [%4];" \
                 : "=r"((r)[0]), "=r"((r)[1]), "=r"((r)[2]), "=r"((r)[3]) : "r"(addr))
#define MMA_BF16(c, a, b0, b1) \
    asm volatile("mma.sync.aligned.m16n8k16.row.col.f32.bf16.bf16.f32 " \
                 "{%0,%1,%2,%3}, {%4,%5,%6,%7}, {%8,%9}, {%0,%1,%2,%3};" \
                 : "+f"((c)[0]), "+f"((c)[1]), "+f"((c)[2]), "+f"((c)[3]) \
                 : "r"((a)[0]), "r"((a)[1]), "r"((a)[2]), "r"((a)[3]), \
                   "r"(b0), "r"(b1))
#define CP16(dst, src) \
    asm volatile("cp.async.cg.shared.global [%0], [%1], 16;" :: "r"(dst), "l"(src))
#define CP_COMMIT() asm volatile("cp.async.commit_group;")
#define CP_WAIT0()  asm volatile("cp.async.wait_group 0;" ::: "memory")

// ---------------------------------------------------------------------------
// Kernel 0: split W into bf16 hi/lo
// ---------------------------------------------------------------------------
__global__ __launch_bounds__(256) void w_split_kernel(
    const float* __restrict__ Wq, const float* __restrict__ Wk,
    const float* __restrict__ Wv)
{
    const int r = blockIdx.x;
    const int c = threadIdx.x;
    const float w = (r < 256) ? Wv[r * 256 + c]
                  : (r < 288) ? Wq[(r - 256) * 256 + c]
                              : Wk[(r - 288) * 256 + c];
    const __nv_bfloat16 h = __float2bfloat16(w);
    const __nv_bfloat16 l = __float2bfloat16(w - __bfloat162float(h));
    g_wh[r * 256 + c] = h;
    g_wl[r * 256 + c] = l;
}

// ---------------------------------------------------------------------------
// Projection GEMM via mma.sync bf16 (3-term hi/lo split, fp32 accumulate).
//   D[p][o] = sum_k X[k][p] * W[o][k] + bias[o]
// ---------------------------------------------------------------------------
template<int NROWS>
__global__ __launch_bounds__(256, 1) void proj_mma_kernel(
    const float* __restrict__ query,
    const float* __restrict__ bq, const float* __restrict__ bk,
    const float* __restrict__ bv)
{
    constexpr int NT   = NROWS / 16;       // n-tiles per warp (8 or 4)
    constexpr int WN   = NROWS / 2;        // warp n extent (64 or 32)
    constexpr int ABUF = 32 * 136 * 2;     // 8704 B
    constexpr int BBUF = NROWS * 40 * 2;   // 10240 or 5120 B

    extern __shared__ char sm[];
    const uint32_t A_H = smem_u32(sm);
    const uint32_t A_L = A_H + 2 * ABUF;
    const uint32_t B_H = A_H + 4 * ABUF;
    const uint32_t B_L = B_H + 2 * BBUF;

    const int tid  = threadIdx.x;
    const int lane = tid & 31;
    const int warp = tid >> 5;
    const int wm   = warp & 3;
    const int wn   = warp >> 2;
    const int g    = lane >> 2;
    const int tg   = lane & 3;

    const int ob = (NROWS == 128) ? (int)blockIdx.x * 128 : 256;
    const int pt = (NROWS == 128) ? (int)blockIdx.y : (int)blockIdx.x;

    const size_t pos0 = (size_t)pt * 128;
    const int b  = (int)(pos0 / HWD);
    const int p0 = (int)(pos0 % HWD);
    const float* Xb = query + (size_t)b * CC * HWD + p0;

    const int aRowL = ((lane >> 4) << 3) + (lane & 7);
    const int aColL = ((lane >> 3) & 1) * 8;
    const int bRowL = aRowL;
    const int bColL = aColL;

    float acc[2][NT][4];
    #pragma unroll
    for (int mt = 0; mt < 2; mt++)
        #pragma unroll
        for (int nt = 0; nt < NT; nt++)
            #pragma unroll
            for (int i = 0; i < 4; i++) acc[mt][nt][i] = 0.f;

    float4 xa[4];

    auto ldga = [&](int t) {
        const int k0 = t * 32;
        #pragma unroll
        for (int j = 0; j < 4; j++) {
            const int f  = tid + j * 256;
            const int kr = f >> 5;
            const int p4 = (f & 31) * 4;
            xa[j] = *(const float4*)(Xb + (size_t)(k0 + kr) * HWD + p4);
        }
    };
    auto stsa = [&](int buf) {
        #pragma unroll
        for (int j = 0; j < 4; j++) {
            const int f  = tid + j * 256;
            const int kr = f >> 5;
            const int p4 = (f & 31) * 4;
            const float xs[4] = {xa[j].x, xa[j].y, xa[j].z, xa[j].w};
            __nv_bfloat16 h[4], l[4];
            #pragma unroll
            for (int e = 0; e < 4; e++) {
                h[e] = __float2bfloat16(xs[e]);
                l[e] = __float2bfloat16(xs[e] - __bfloat162float(h[e]));
            }
            const uint32_t off = (uint32_t)(kr * 136 + p4) * 2;
            uint32_t dh = A_H + buf * ABUF + off;
            uint32_t dl = A_L + buf * ABUF + off;
            uint2 vh = make_uint2(pack_bf2(h[0], h[1]), pack_bf2(h[2], h[3]));
            uint2 vl = make_uint2(pack_bf2(l[0], l[1]), pack_bf2(l[2], l[3]));
            asm volatile("st.shared.v2.u32 [%0], {%1,%2};" :: "r"(dh), "r"(vh.x), "r"(vh.y));
            asm volatile("st.shared.v2.u32 [%0], {%1,%2};" :: "r"(dl), "r"(vl.x), "r"(vl.y));
        }
    };
    auto cpb = [&](int t, int buf) {
        const int k0 = t * 32;
        constexpr int CH = NROWS * 4;
        #pragma unroll
        for (int j = 0; j < CH / 256; j++) {
            const int id  = tid + j * 256;
            const int row = id >> 2;
            const int seg = id & 3;
            const uint32_t doff = (uint32_t)(row * 40 + seg * 8) * 2;
            CP16(B_H + buf * BBUF + doff, &g_wh[(size_t)(ob + row) * 256 + k0 + seg * 8]);
            CP16(B_L + buf * BBUF + doff, &g_wl[(size_t)(ob + row) * 256 + k0 + seg * 8]);
        }
    };
    auto compute = [&](int buf) {
        #pragma unroll
        for (int k16 = 0; k16 < 32; k16 += 16) {
            uint32_t ah[2][4], al[2][4];
            #pragma unroll
            for (int mt = 0; mt < 2; mt++) {
                const uint32_t off =
                    (uint32_t)((k16 + aRowL) * 136 + wm * 32 + mt * 16 + aColL) * 2;
                LDSM_T(ah[mt], A_H + buf * ABUF + off);
                LDSM_T(al[mt], A_L + buf * ABUF + off);
            }
            uint32_t bh[NT / 2][4], bl[NT / 2][4];
            #pragma unroll
            for (int np = 0; np < NT / 2; np++) {
                const uint32_t off =
                    (uint32_t)((wn * WN + np * 16 + bRowL) * 40 + k16 + bColL) * 2;
                LDSM_N(bh[np], B_H + buf * BBUF + off);
                LDSM_N(bl[np], B_L + buf * BBUF + off);
            }
            #pragma unroll
            for (int mt = 0; mt < 2; mt++)
                #pragma unroll
                for (int np = 0; np < NT / 2; np++)
                    #pragma unroll
                    for (int h = 0; h < 2; h++) {
                        const int nt = np * 2 + h;
                        MMA_BF16(acc[mt][nt], ah[mt], bh[np][h*2], bh[np][h*2+1]);
                        MMA_BF16(acc[mt][nt], ah[mt], bl[np][h*2], bl[np][h*2+1]);
                        MMA_BF16(acc[mt][nt], al[mt], bh[np][h*2], bh[np][h*2+1]);
                    }
        }
    };

    ldga(0);
    cpb(0, 0);
    CP_COMMIT();
    stsa(0);
    CP_WAIT0();
    __syncthreads();

    #pragma unroll 1
    for (int t = 0; t < 8; t++) {
        if (t < 7) {
            ldga(t + 1);
            cpb(t + 1, (t + 1) & 1);
            CP_COMMIT();
        }
        compute(t & 1);
        if (t < 7) stsa((t + 1) & 1);
        CP_WAIT0();
        __syncthreads();
    }

    #pragma unroll
    for (int mt = 0; mt < 2; mt++) {
        const size_t prow = pos0 + wm * 32 + mt * 16 + g;
        #pragma unroll
        for (int nt = 0; nt < NT; nt++) {
            const int n = wn * WN + nt * 8 + tg * 2;
            if (NROWS == 128) {
                const int oc = (int)blockIdx.x * 128 + n;
                const float b0 = bv[oc], b1 = bv[oc + 1];
                *(float2*)&g_v[prow * CC + oc] =
                    make_float2(acc[mt][nt][0] + b0, acc[mt][nt][1] + b1);
                *(float2*)&g_v[(prow + 8) * CC + oc] =
                    make_float2(acc[mt][nt][2] + b0, acc[mt][nt][3] + b1);
            } else {
                if (n < 32) {
                    const float b0 = bq[n], b1 = bq[n + 1];
                    *(float2*)&g_q[prow * EE + n] =
                        make_float2(acc[mt][nt][0] + b0, acc[mt][nt][1] + b1);
                    *(float2*)&g_q[(prow + 8) * EE + n] =
                        make_float2(acc[mt][nt][2] + b0, acc[mt][nt][3] + b1);
                } else {
                    const float b0 = bk[n - 32], b1 = bk[n - 31];
                    *(float2*)&g_k[prow * EE + n - 32] =
                        make_float2(acc[mt][nt][0] + b0, acc[mt][nt][1] + b1);
                    *(float2*)&g_k[(prow + 8) * EE + n - 32] =
                        make_float2(acc[mt][nt][2] + b0, acc[mt][nt][3] + b1);
                }
            }
        }
    }
}

// ---------------------------------------------------------------------------
// Kernel 2: raw logits per axis (q.k over 48-line), eH diagonal masked.
// Padded smem (33-float rows) kills the 32-way bank conflicts; 3x3 register
// tile: thread (xg=tid>>4, yg=tid&15) computes {xg,+16,+32} x {yg,+16,+32}.
// ---------------------------------------------------------------------------
__global__ __launch_bounds__(256) void logits_kernel()
{
    const int l    = blockIdx.x;
    const int axis = blockIdx.y;
    const int b    = blockIdx.z;
    const int tid  = threadIdx.x;

    __shared__ float Qs[48][33];
    __shared__ float Ks[48][33];

    const int a1 = l / 48, a2 = l % 48;
    int base, stride;
    if      (axis == 0) { base = a1 * 48 + a2;      stride = WD; }
    else if (axis == 1) { base = a1 * WD + a2;      stride = 48; }
    else                { base = a1 * WD + a2 * 48; stride = 1;  }

    const size_t b0 = (size_t)b * HWD;

    for (int f = tid; f < 48 * 32; f += 256) {
        const int y = f >> 5, e = f & 31;
        const size_t p = b0 + base + (size_t)y * stride;
        Qs[y][e] = g_q[p * EE + e];
        Ks[y][e] = g_k[p * EE + e];
    }
    __syncthreads();

    const int xg = tid >> 4;   // 0..15
    const int yg = tid & 15;   // 0..15

    float acc[3][3];
    #pragma unroll
    for (int i = 0; i < 3; i++)
        #pragma unroll
        for (int j = 0; j < 3; j++) acc[i][j] = 0.f;

    #pragma unroll
    for (int e = 0; e < 32; e++) {
        float qv[3], kv[3];
        #pragma unroll
        for (int i = 0; i < 3; i++) qv[i] = Qs[xg + 16 * i][e];
        #pragma unroll
        for (int j = 0; j < 3; j++) kv[j] = Ks[yg + 16 * j][e];
        #pragma unroll
        for (int i = 0; i < 3; i++)
            #pragma unroll
            for (int j = 0; j < 3; j++)
                acc[i][j] += qv[i] * kv[j];
    }

    #pragma unroll
    for (int i = 0; i < 3; i++) {
        const int x = xg + 16 * i;
        const size_t p = b0 + base + (size_t)x * stride;
        float* dst = &g_att[p * NL + axis * 48];
        #pragma unroll
        for (int j = 0; j < 3; j++) {
            const int y = yg + 16 * j;
            dst[y] = (axis == 0 && x == y) ? -3.0e38f : acc[i][j];
        }
    }
}

// ---------------------------------------------------------------------------
// Kernel 3: per-position softmax stats (max, 1/sum) over 144 logits.
// ---------------------------------------------------------------------------
__global__ __launch_bounds__(256) void mz_kernel()
{
    const int tid  = threadIdx.x;
    const int pos  = blockIdx.x * 32 + (tid >> 3);
    const int lane = tid & 7;
    const float* row = g_att + (size_t)pos * NL;

    float4 v[5];
    float m = -3.4e38f;
    #pragma unroll
    for (int k = 0; k < 5; k++) {
        const int j = lane + k * 8;
        if (j < 36) {
            v[k] = *(const float4*)&row[j * 4];
            m = fmaxf(m, fmaxf(fmaxf(v[k].x, v[k].y), fmaxf(v[k].z, v[k].w)));
        }
    }
    #pragma unroll
    for (int o = 1; o < 8; o <<= 1)
        m = fmaxf(m, __shfl_xor_sync(0xffffffffu, m, o));

    float s = 0.f;
    #pragma unroll
    for (int k = 0; k < 5; k++) {
        const int j = lane + k * 8;
        if (j < 36) {
            s += expf(v[k].x - m) + expf(v[k].y - m)
               + expf(v[k].z - m) + expf(v[k].w - m);
        }
    }
    #pragma unroll
    for (int o = 1; o < 8; o <<= 1)
        s += __shfl_xor_sync(0xffffffffu, s, o);

    if (lane == 0) g_mz[pos] = make_float2(m, 1.f / s);
}

// ---------------------------------------------------------------------------
// Kernel 4/5/6: aggregation per axis (normalizes logits on the fly).
// ---------------------------------------------------------------------------
template<int AXIS>
__global__ __launch_bounds__(512) void agg_kernel(
    const float* __restrict__ query,
    const float* __restrict__ gamma,
    float* __restrict__ out)
{
    extern __shared__ float smf[];
    float  (*Vs)[256] = (float (*)[256])smf;              // 48x256
    float  (*As)[48]  = (float (*)[48])(smf + 48 * 256);  // 48x48
    float2* mzs       = (float2*)(smf + 48 * 256 + 48 * 48);

    const int l   = blockIdx.x;
    const int b   = blockIdx.y;
    const int tid = threadIdx.x;

    const int a1 = l / 48, a2 = l % 48;
    int base, stride;
    if      (AXIS == 0) { base = a1 * 48 + a2;      stride = WD; }
    else if (AXIS == 1) { base = a1 * WD + a2;      stride = 48; }
    else                { base = a1 * WD + a2 * 48; stride = 1;  }

    const size_t b0 = (size_t)b * HWD;

    if (tid < 48) mzs[tid] = g_mz[b0 + base + (size_t)tid * stride];

    #pragma unroll
    for (int k = 0; k < 6; k++) {
        const int f  = tid + k * 512;
        const int y  = f >> 6;
        const int c4 = f & 63;
        *(float4*)&Vs[y][c4 * 4] =
            *(const float4*)&g_v[(b0 + base + (size_t)y * stride) * CC + c4 * 4];
    }
    __syncthreads();

    for (int f = tid; f < 48 * 48; f += 512) {
        const int x = f / 48, y = f % 48;
        const float raw = g_att[(b0 + base + (size_t)x * stride) * NL + AXIS * 48 + y];
        const float2 mz = mzs[x];
        As[x][y] = expf(raw - mz.x) * mz.y;
    }
    __syncthreads();

    const int cg = tid & 31;
    const int ca = cg * 4;
    const int xg = tid >> 5;
    const int x0 = xg * 3;

    float acc[3][8];
    #pragma unroll
    for (int i = 0; i < 3; i++)
        #pragma unroll
        for (int j = 0; j < 8; j++) acc[i][j] = 0.f;

    #pragma unroll 2
    for (int y = 0; y < 48; y++) {
        const float4 v0 = *(const float4*)&Vs[y][ca];
        const float4 v1 = *(const float4*)&Vs[y][ca + 128];
        #pragma unroll
        for (int xi = 0; xi < 3; xi++) {
            const float a = As[x0 + xi][y];
            acc[xi][0] += a * v0.x; acc[xi][1] += a * v0.y;
            acc[xi][2] += a * v0.z; acc[xi][3] += a * v0.w;
            acc[xi][4] += a * v1.x; acc[xi][5] += a * v1.y;
            acc[xi][6] += a * v1.z; acc[xi][7] += a * v1.w;
        }
    }

    if (AXIS == 0) {
        #pragma unroll
        for (int xi = 0; xi < 3; xi++) {
            const size_t p = b0 + base + (size_t)(x0 + xi) * stride;
            *(float4*)&g_acc[p * CC + ca]       = make_float4(acc[xi][0], acc[xi][1], acc[xi][2], acc[xi][3]);
            *(float4*)&g_acc[p * CC + ca + 128] = make_float4(acc[xi][4], acc[xi][5], acc[xi][6], acc[xi][7]);
        }
    } else if (AXIS == 1) {
        #pragma unroll
        for (int xi = 0; xi < 3; xi++) {
            const size_t p = b0 + base + (size_t)(x0 + xi) * stride;
            float4 a0 = *(const float4*)&g_acc[p * CC + ca];
            float4 a1 = *(const float4*)&g_acc[p * CC + ca + 128];
            a0.x += acc[xi][0]; a0.y += acc[xi][1]; a0.z += acc[xi][2]; a0.w += acc[xi][3];
            a1.x += acc[xi][4]; a1.y += acc[xi][5]; a1.z += acc[xi][6]; a1.w += acc[xi][7];
            *(float4*)&g_acc[p * CC + ca]       = a0;
            *(float4*)&g_acc[p * CC + ca + 128] = a1;
        }
    } else {
        __syncthreads();
        float (*Rs)[256] = Vs;
        #pragma unroll
        for (int xi = 0; xi < 3; xi++) {
            const int x = x0 + xi;
            const size_t p = b0 + base + x;     // stride 1
            const float4 a0 = *(const float4*)&g_acc[p * CC + ca];
            const float4 a1 = *(const float4*)&g_acc[p * CC + ca + 128];
            *(float4*)&Rs[x][ca] = make_float4(acc[xi][0] + a0.x, acc[xi][1] + a0.y,
                                               acc[xi][2] + a0.z, acc[xi][3] + a0.w);
            *(float4*)&Rs[x][ca + 128] = make_float4(acc[xi][4] + a1.x, acc[xi][5] + a1.y,
                                                     acc[xi][6] + a1.z, acc[xi][7] + a1.w);
        }
        __syncthreads();

        const float gm = gamma[0];
        const int c  = tid & 255;
        const int xh = tid >> 8;
        const size_t gidx = ((size_t)b * CC + c) * HWD + base;
        #pragma unroll 4
        for (int x = xh * 24; x < xh * 24 + 24; x++) {
            out[gidx + x] = gm * Rs[x][c] + query[gidx + x];
        }
    }
}

// ---------------------------------------------------------------------------
extern "C" void kernel_launch(void* const* d_in, const int* in_sizes, int n_in,
                              void* d_out, int out_size)
{
    const float* query = (const float*)d_in[0];
    const float* Wq    = (const float*)d_in[1];
    const float* bq    = (const float*)d_in[2];
    const float* Wk    = (const float*)d_in[3];
    const float* bk    = (const float*)d_in[4];
    const float* Wv    = (const float*)d_in[5];
    const float* bv    = (const float*)d_in[6];
    const float* gamma = (const float*)d_in[7];
    float* out = (float*)d_out;
    (void)in_sizes; (void)n_in; (void)out_size;

    const int SMEM_V  = 4 * 8704 + 4 * (128 * 40 * 2);  // 75776
    const int SMEM_QK = 4 * 8704 + 4 * (64 * 40 * 2);   // 55296
    const int AGG_SMEM = (48 * 256 + 48 * 48) * 4 + 48 * 8;   // 58752

    cudaFuncSetAttribute(proj_mma_kernel<128>, cudaFuncAttributeMaxDynamicSharedMemorySize, SMEM_V);
    cudaFuncSetAttribute(proj_mma_kernel<64>,  cudaFuncAttributeMaxDynamicSharedMemorySize, SMEM_QK);
    cudaFuncSetAttribute(agg_kernel<0>, cudaFuncAttributeMaxDynamicSharedMemorySize, AGG_SMEM);
    cudaFuncSetAttribute(agg_kernel<1>, cudaFuncAttributeMaxDynamicSharedMemorySize, AGG_SMEM);
    cudaFuncSetAttribute(agg_kernel<2>, cudaFuncAttributeMaxDynamicSharedMemorySize, AGG_SMEM);

    w_split_kernel<<<320, 256>>>(Wq, Wk, Wv);
    proj_mma_kernel<128><<<dim3(2, NP / 128), 256, SMEM_V>>>(query, bq, bk, bv);
    proj_mma_kernel<64> <<<NP / 128, 256, SMEM_QK>>>(query, bq, bk, bv);
    logits_kernel <<<dim3(WD, 3, BB), 256>>>();
    mz_kernel     <<<NP / 32, 256>>>();
    agg_kernel<0> <<<dim3(WD, BB), 512, AGG_SMEM>>>(query, gamma, out);
    agg_kernel<1> <<<dim3(WD, BB), 512, AGG_SMEM>>>(query, gamma, out);
    agg_kernel<2> <<<dim3(WD, BB), 512, AGG_SMEM>>>(query, gamma, out);
}

// round 7
// speedup vs baseline: 2.0525x; 1.0298x over previous
#include <cuda_runtime.h>
#include <cuda_bf16.h>
#include <math.h>
#include <stdint.h>

// Problem constants
#define BB   2
#define CC   256
#define EE   32
#define WD   2304      // W*D
#define HWD  110592    // H*W*D
#define NP   221184    // B*HWD
#define NL   144       // 3*48 logits per position

// ---------------------------------------------------------------------------
// Scratch (device globals: allocation-free rule)
// ---------------------------------------------------------------------------
__device__ float         g_q  [(size_t)NP * EE];
__device__ float         g_k  [(size_t)NP * EE];
__device__ float         g_v  [(size_t)NP * CC];
__device__ float         g_att[(size_t)NP * NL];
__device__ float2        g_mz [(size_t)NP];
__device__ float         g_acc[(size_t)NP * CC];
// W rows: 0..255 = Wv, 256..287 = Wq, 288..319 = Wk  (bf16 hi/lo split)
__device__ __nv_bfloat16 g_wh [320 * 256];
__device__ __nv_bfloat16 g_wl [320 * 256];

__device__ __forceinline__ uint32_t smem_u32(const void* p) {
    uint32_t a;
    asm("{ .reg .u64 t; cvta.to.shared.u64 t, %1; cvt.u32.u64 %0, t; }"
        : "=r"(a) : "l"(p));
    return a;
}

__device__ __forceinline__ uint32_t pack_bf2(__nv_bfloat16 a, __nv_bfloat16 b) {
    return (uint32_t)__bfloat16_as_ushort(a)
         | ((uint32_t)__bfloat16_as_ushort(b) << 16);
}

#define LDSM_T(r, addr) \
    asm volatile("ldmatrix.sync.aligned.m8n8.x4.trans.shared.b16 {%0,%1,%2,%3}, [%4];" \
                 : "=r"((r)[0]), "=r"((r)[1]), "=r"((r)[2]), "=r"((r)[3]) : "r"(addr))
#define LDSM_N(r, addr) \
    asm volatile("ldmatrix.sync.aligned.m8n8.x4.shared.b16 {%0,%1,%2,%3}, [%4];" \
                 : "=r"((r)[0]), "=r"((r)[1]), "=r"((r)[2]), "=r"((r)[3]) : "r"(addr))
#define MMA_BF16(c, a, b0, b1) \
    asm volatile("mma.sync.aligned.m16n8k16.row.col.f32.bf16.bf16.f32 " \
                 "{%0,%1,%2,%3}, {%4,%5,%6,%7}, {%8,%9}, {%0,%1,%2,%3};" \
                 : "+f"((c)[0]), "+f"((c)[1]), "+f"((c)[2]), "+f"((c)[3]) \
                 : "r"((a)[0]), "r"((a)[1]), "r"((a)[2]), "r"((a)[3]), \
                   "r"(b0), "r"(b1))
#define CP16(dst, src) \
    asm volatile("cp.async.cg.shared.global [%0], [%1], 16;" :: "r"(dst), "l"(src))
#define CP_COMMIT() asm volatile("cp.async.commit_group;")
#define CP_WAIT0()  asm volatile("cp.async.wait_group 0;" ::: "memory")

// ---------------------------------------------------------------------------
// Kernel 0: split W into bf16 hi/lo
// ---------------------------------------------------------------------------
__global__ __launch_bounds__(256) void w_split_kernel(
    const float* __restrict__ Wq, const float* __restrict__ Wk,
    const float* __restrict__ Wv)
{
    const int r = blockIdx.x;
    const int c = threadIdx.x;
    const float w = (r < 256) ? Wv[r * 256 + c]
                  : (r < 288) ? Wq[(r - 256) * 256 + c]
                              : Wk[(r - 288) * 256 + c];
    const __nv_bfloat16 h = __float2bfloat16(w);
    const __nv_bfloat16 l = __float2bfloat16(w - __bfloat162float(h));
    g_wh[r * 256 + c] = h;
    g_wl[r * 256 + c] = l;
}

// ---------------------------------------------------------------------------
// Fused QKV projection GEMM via mma.sync bf16 (3-term hi/lo split).
//   D[p][o] = sum_k X[k][p] * W[o][k] + bias[o],  o in [0,320)
// Grid (2, NP/128): block bx covers output rows [bx*160, bx*160+160).
// CTA tile: 128 positions x 160 outputs, K = 256 in 8 stages of 32.
// A (X) staged [k][136p] bf16 hi/lo -> ldmatrix.x4.trans
// B (W) staged [o][40k]  bf16 hi/lo -> ldmatrix.x4 (via cp.async)
// Warps 4(m) x 2(n); warp tile 32p x 80o (NT=10 tiles of 8).
// ---------------------------------------------------------------------------
#define NROWS 160
#define NT    10          // n-tiles of 8 per warp
#define WN    80          // warp n extent
#define ABUF  (32 * 136 * 2)   // 8704 B
#define BBUF  (NROWS * 40 * 2) // 12800 B
#define PROJ_SMEM (4 * ABUF + 4 * BBUF)   // 86016 B

__global__ __launch_bounds__(256, 1) void proj_mma_kernel(
    const float* __restrict__ query,
    const float* __restrict__ bq, const float* __restrict__ bk,
    const float* __restrict__ bv)
{
    extern __shared__ char sm[];
    const uint32_t A_H = smem_u32(sm);
    const uint32_t A_L = A_H + 2 * ABUF;
    const uint32_t B_H = A_H + 4 * ABUF;
    const uint32_t B_L = B_H + 2 * BBUF;

    __shared__ float s_bias[NROWS];

    const int tid  = threadIdx.x;
    const int lane = tid & 31;
    const int warp = tid >> 5;
    const int wm   = warp & 3;
    const int wn   = warp >> 2;
    const int g    = lane >> 2;
    const int tg   = lane & 3;

    const int ob = (int)blockIdx.x * NROWS;   // global W row base
    const size_t pos0 = (size_t)blockIdx.y * 128;
    const int b  = (int)(pos0 / HWD);
    const int p0 = (int)(pos0 % HWD);
    const float* Xb = query + (size_t)b * CC * HWD + p0;

    // stage bias for this block's rows
    if (tid < NROWS) {
        const int o = ob + tid;
        s_bias[tid] = (o < 256) ? bv[o] : (o < 288) ? bq[o - 256] : bk[o - 288];
    }

    const int aRowL = ((lane >> 4) << 3) + (lane & 7);
    const int aColL = ((lane >> 3) & 1) * 8;
    const int bRowL = aRowL;
    const int bColL = aColL;

    float acc[2][NT][4];
    #pragma unroll
    for (int mt = 0; mt < 2; mt++)
        #pragma unroll
        for (int nt = 0; nt < NT; nt++)
            #pragma unroll
            for (int i = 0; i < 4; i++) acc[mt][nt][i] = 0.f;

    float4 xa[4];

    auto ldga = [&](int t) {
        const int k0 = t * 32;
        #pragma unroll
        for (int j = 0; j < 4; j++) {
            const int f  = tid + j * 256;
            const int kr = f >> 5;
            const int p4 = (f & 31) * 4;
            xa[j] = *(const float4*)(Xb + (size_t)(k0 + kr) * HWD + p4);
        }
    };
    auto stsa = [&](int buf) {
        #pragma unroll
        for (int j = 0; j < 4; j++) {
            const int f  = tid + j * 256;
            const int kr = f >> 5;
            const int p4 = (f & 31) * 4;
            const float xs[4] = {xa[j].x, xa[j].y, xa[j].z, xa[j].w};
            __nv_bfloat16 h[4], l[4];
            #pragma unroll
            for (int e = 0; e < 4; e++) {
                h[e] = __float2bfloat16(xs[e]);
                l[e] = __float2bfloat16(xs[e] - __bfloat162float(h[e]));
            }
            const uint32_t off = (uint32_t)(kr * 136 + p4) * 2;
            uint32_t dh = A_H + buf * ABUF + off;
            uint32_t dl = A_L + buf * ABUF + off;
            uint2 vh = make_uint2(pack_bf2(h[0], h[1]), pack_bf2(h[2], h[3]));
            uint2 vl = make_uint2(pack_bf2(l[0], l[1]), pack_bf2(l[2], l[3]));
            asm volatile("st.shared.v2.u32 [%0], {%1,%2};" :: "r"(dh), "r"(vh.x), "r"(vh.y));
            asm volatile("st.shared.v2.u32 [%0], {%1,%2};" :: "r"(dl), "r"(vl.x), "r"(vl.y));
        }
    };
    auto cpb = [&](int t, int buf) {
        const int k0 = t * 32;
        // NROWS*4 = 640 16B chunks per (hi|lo)
        for (int id = tid; id < NROWS * 4; id += 256) {
            const int row = id >> 2;
            const int seg = id & 3;
            const uint32_t doff = (uint32_t)(row * 40 + seg * 8) * 2;
            CP16(B_H + buf * BBUF + doff, &g_wh[(size_t)(ob + row) * 256 + k0 + seg * 8]);
            CP16(B_L + buf * BBUF + doff, &g_wl[(size_t)(ob + row) * 256 + k0 + seg * 8]);
        }
    };
    auto compute = [&](int buf) {
        #pragma unroll
        for (int k16 = 0; k16 < 32; k16 += 16) {
            uint32_t ah[2][4], al[2][4];
            #pragma unroll
            for (int mt = 0; mt < 2; mt++) {
                const uint32_t off =
                    (uint32_t)((k16 + aRowL) * 136 + wm * 32 + mt * 16 + aColL) * 2;
                LDSM_T(ah[mt], A_H + buf * ABUF + off);
                LDSM_T(al[mt], A_L + buf * ABUF + off);
            }
            uint32_t bh[NT / 2][4], bl[NT / 2][4];
            #pragma unroll
            for (int np = 0; np < NT / 2; np++) {
                const uint32_t off =
                    (uint32_t)((wn * WN + np * 16 + bRowL) * 40 + k16 + bColL) * 2;
                LDSM_N(bh[np], B_H + buf * BBUF + off);
                LDSM_N(bl[np], B_L + buf * BBUF + off);
            }
            #pragma unroll
            for (int mt = 0; mt < 2; mt++)
                #pragma unroll
                for (int np = 0; np < NT / 2; np++)
                    #pragma unroll
                    for (int h = 0; h < 2; h++) {
                        const int nt = np * 2 + h;
                        MMA_BF16(acc[mt][nt], ah[mt], bh[np][h*2], bh[np][h*2+1]);
                        MMA_BF16(acc[mt][nt], ah[mt], bl[np][h*2], bl[np][h*2+1]);
                        MMA_BF16(acc[mt][nt], al[mt], bh[np][h*2], bh[np][h*2+1]);
                    }
        }
    };

    ldga(0);
    cpb(0, 0);
    CP_COMMIT();
    stsa(0);
    CP_WAIT0();
    __syncthreads();

    #pragma unroll 1
    for (int t = 0; t < 8; t++) {
        if (t < 7) {
            ldga(t + 1);
            cpb(t + 1, (t + 1) & 1);
            CP_COMMIT();
        }
        compute(t & 1);
        if (t < 7) stsa((t + 1) & 1);
        CP_WAIT0();
        __syncthreads();
    }

    // ---- epilogue: route rows <256 -> g_v, <288 -> g_q, else -> g_k ----
    #pragma unroll
    for (int mt = 0; mt < 2; mt++) {
        const size_t prow = pos0 + wm * 32 + mt * 16 + g;
        #pragma unroll
        for (int nt = 0; nt < NT; nt++) {
            const int nl = wn * WN + nt * 8 + tg * 2;   // local row in block
            const int n  = ob + nl;                     // global output row
            const float b0 = s_bias[nl], b1 = s_bias[nl + 1];
            const float2 r0 = make_float2(acc[mt][nt][0] + b0, acc[mt][nt][1] + b1);
            const float2 r1 = make_float2(acc[mt][nt][2] + b0, acc[mt][nt][3] + b1);
            if (n < 256) {
                *(float2*)&g_v[prow * CC + n]       = r0;
                *(float2*)&g_v[(prow + 8) * CC + n] = r1;
            } else if (n < 288) {
                *(float2*)&g_q[prow * EE + n - 256]       = r0;
                *(float2*)&g_q[(prow + 8) * EE + n - 256] = r1;
            } else {
                *(float2*)&g_k[prow * EE + n - 288]       = r0;
                *(float2*)&g_k[(prow + 8) * EE + n - 288] = r1;
            }
        }
    }
}

// ---------------------------------------------------------------------------
// Kernel 2: raw logits per axis (q.k over 48-line), eH diagonal masked.
// ---------------------------------------------------------------------------
__global__ __launch_bounds__(256) void logits_kernel()
{
    const int l    = blockIdx.x;
    const int axis = blockIdx.y;
    const int b    = blockIdx.z;
    const int tid  = threadIdx.x;

    __shared__ float Qs[48][33];
    __shared__ float Ks[48][33];

    const int a1 = l / 48, a2 = l % 48;
    int base, stride;
    if      (axis == 0) { base = a1 * 48 + a2;      stride = WD; }
    else if (axis == 1) { base = a1 * WD + a2;      stride = 48; }
    else                { base = a1 * WD + a2 * 48; stride = 1;  }

    const size_t b0 = (size_t)b * HWD;

    for (int f = tid; f < 48 * 32; f += 256) {
        const int y = f >> 5, e = f & 31;
        const size_t p = b0 + base + (size_t)y * stride;
        Qs[y][e] = g_q[p * EE + e];
        Ks[y][e] = g_k[p * EE + e];
    }
    __syncthreads();

    const int xg = tid >> 4;
    const int yg = tid & 15;

    float acc[3][3];
    #pragma unroll
    for (int i = 0; i < 3; i++)
        #pragma unroll
        for (int j = 0; j < 3; j++) acc[i][j] = 0.f;

    #pragma unroll
    for (int e = 0; e < 32; e++) {
        float qv[3], kv[3];
        #pragma unroll
        for (int i = 0; i < 3; i++) qv[i] = Qs[xg + 16 * i][e];
        #pragma unroll
        for (int j = 0; j < 3; j++) kv[j] = Ks[yg + 16 * j][e];
        #pragma unroll
        for (int i = 0; i < 3; i++)
            #pragma unroll
            for (int j = 0; j < 3; j++)
                acc[i][j] += qv[i] * kv[j];
    }

    #pragma unroll
    for (int i = 0; i < 3; i++) {
        const int x = xg + 16 * i;
        const size_t p = b0 + base + (size_t)x * stride;
        float* dst = &g_att[p * NL + axis * 48];
        #pragma unroll
        for (int j = 0; j < 3; j++) {
            const int y = yg + 16 * j;
            dst[y] = (axis == 0 && x == y) ? -3.0e38f : acc[i][j];
        }
    }
}

// ---------------------------------------------------------------------------
// Kernel 3: per-position softmax stats (max, 1/sum) over 144 logits.
// ---------------------------------------------------------------------------
__global__ __launch_bounds__(256) void mz_kernel()
{
    const int tid  = threadIdx.x;
    const int pos  = blockIdx.x * 32 + (tid >> 3);
    const int lane = tid & 7;
    const float* row = g_att + (size_t)pos * NL;

    float4 v[5];
    float m = -3.4e38f;
    #pragma unroll
    for (int k = 0; k < 5; k++) {
        const int j = lane + k * 8;
        if (j < 36) {
            v[k] = *(const float4*)&row[j * 4];
            m = fmaxf(m, fmaxf(fmaxf(v[k].x, v[k].y), fmaxf(v[k].z, v[k].w)));
        }
    }
    #pragma unroll
    for (int o = 1; o < 8; o <<= 1)
        m = fmaxf(m, __shfl_xor_sync(0xffffffffu, m, o));

    float s = 0.f;
    #pragma unroll
    for (int k = 0; k < 5; k++) {
        const int j = lane + k * 8;
        if (j < 36) {
            s += expf(v[k].x - m) + expf(v[k].y - m)
               + expf(v[k].z - m) + expf(v[k].w - m);
        }
    }
    #pragma unroll
    for (int o = 1; o < 8; o <<= 1)
        s += __shfl_xor_sync(0xffffffffu, s, o);

    if (lane == 0) g_mz[pos] = make_float2(m, 1.f / s);
}

// ---------------------------------------------------------------------------
// Kernel 4/5/6: aggregation per axis (normalizes logits on the fly).
// ---------------------------------------------------------------------------
template<int AXIS>
__global__ __launch_bounds__(512) void agg_kernel(
    const float* __restrict__ query,
    const float* __restrict__ gamma,
    float* __restrict__ out)
{
    extern __shared__ float smf[];
    float  (*Vs)[256] = (float (*)[256])smf;              // 48x256
    float  (*As)[48]  = (float (*)[48])(smf + 48 * 256);  // 48x48
    float2* mzs       = (float2*)(smf + 48 * 256 + 48 * 48);

    const int l   = blockIdx.x;
    const int b   = blockIdx.y;
    const int tid = threadIdx.x;

    const int a1 = l / 48, a2 = l % 48;
    int base, stride;
    if      (AXIS == 0) { base = a1 * 48 + a2;      stride = WD; }
    else if (AXIS == 1) { base = a1 * WD + a2;      stride = 48; }
    else                { base = a1 * WD + a2 * 48; stride = 1;  }

    const size_t b0 = (size_t)b * HWD;

    if (tid < 48) mzs[tid] = g_mz[b0 + base + (size_t)tid * stride];

    #pragma unroll
    for (int k = 0; k < 6; k++) {
        const int f  = tid + k * 512;
        const int y  = f >> 6;
        const int c4 = f & 63;
        *(float4*)&Vs[y][c4 * 4] =
            *(const float4*)&g_v[(b0 + base + (size_t)y * stride) * CC + c4 * 4];
    }
    __syncthreads();

    for (int f = tid; f < 48 * 48; f += 512) {
        const int x = f / 48, y = f % 48;
        const float raw = g_att[(b0 + base + (size_t)x * stride) * NL + AXIS * 48 + y];
        const float2 mz = mzs[x];
        As[x][y] = expf(raw - mz.x) * mz.y;
    }
    __syncthreads();

    const int cg = tid & 31;
    const int ca = cg * 4;
    const int xg = tid >> 5;
    const int x0 = xg * 3;

    float acc[3][8];
    #pragma unroll
    for (int i = 0; i < 3; i++)
        #pragma unroll
        for (int j = 0; j < 8; j++) acc[i][j] = 0.f;

    #pragma unroll 2
    for (int y = 0; y < 48; y++) {
        const float4 v0 = *(const float4*)&Vs[y][ca];
        const float4 v1 = *(const float4*)&Vs[y][ca + 128];
        #pragma unroll
        for (int xi = 0; xi < 3; xi++) {
            const float a = As[x0 + xi][y];
            acc[xi][0] += a * v0.x; acc[xi][1] += a * v0.y;
            acc[xi][2] += a * v0.z; acc[xi][3] += a * v0.w;
            acc[xi][4] += a * v1.x; acc[xi][5] += a * v1.y;
            acc[xi][6] += a * v1.z; acc[xi][7] += a * v1.w;
        }
    }

    if (AXIS == 0) {
        #pragma unroll
        for (int xi = 0; xi < 3; xi++) {
            const size_t p = b0 + base + (size_t)(x0 + xi) * stride;
            *(float4*)&g_acc[p * CC + ca]       = make_float4(acc[xi][0], acc[xi][1], acc[xi][2], acc[xi][3]);
            *(float4*)&g_acc[p * CC + ca + 128] = make_float4(acc[xi][4], acc[xi][5], acc[xi][6], acc[xi][7]);
        }
    } else if (AXIS == 1) {
        #pragma unroll
        for (int xi = 0; xi < 3; xi++) {
            const size_t p = b0 + base + (size_t)(x0 + xi) * stride;
            float4 a0 = *(const float4*)&g_acc[p * CC + ca];
            float4 a1 = *(const float4*)&g_acc[p * CC + ca + 128];
            a0.x += acc[xi][0]; a0.y += acc[xi][1]; a0.z += acc[xi][2]; a0.w += acc[xi][3];
            a1.x += acc[xi][4]; a1.y += acc[xi][5]; a1.z += acc[xi][6]; a1.w += acc[xi][7];
            *(float4*)&g_acc[p * CC + ca]       = a0;
            *(float4*)&g_acc[p * CC + ca + 128] = a1;
        }
    } else {
        __syncthreads();
        float (*Rs)[256] = Vs;
        #pragma unroll
        for (int xi = 0; xi < 3; xi++) {
            const int x = x0 + xi;
            const size_t p = b0 + base + x;     // stride 1
            const float4 a0 = *(const float4*)&g_acc[p * CC + ca];
            const float4 a1 = *(const float4*)&g_acc[p * CC + ca + 128];
            *(float4*)&Rs[x][ca] = make_float4(acc[xi][0] + a0.x, acc[xi][1] + a0.y,
                                               acc[xi][2] + a0.z, acc[xi][3] + a0.w);
            *(float4*)&Rs[x][ca + 128] = make_float4(acc[xi][4] + a1.x, acc[xi][5] + a1.y,
                                                     acc[xi][6] + a1.z, acc[xi][7] + a1.w);
        }
        __syncthreads();

        const float gm = gamma[0];
        const int c  = tid & 255;
        const int xh = tid >> 8;
        const size_t gidx = ((size_t)b * CC + c) * HWD + base;
        #pragma unroll 4
        for (int x = xh * 24; x < xh * 24 + 24; x++) {
            out[gidx + x] = gm * Rs[x][c] + query[gidx + x];
        }
    }
}

// ---------------------------------------------------------------------------
extern "C" void kernel_launch(void* const* d_in, const int* in_sizes, int n_in,
                              void* d_out, int out_size)
{
    const float* query = (const float*)d_in[0];
    const float* Wq    = (const float*)d_in[1];
    const float* bq    = (const float*)d_in[2];
    const float* Wk    = (const float*)d_in[3];
    const float* bk    = (const float*)d_in[4];
    const float* Wv    = (const float*)d_in[5];
    const float* bv    = (const float*)d_in[6];
    const float* gamma = (const float*)d_in[7];
    float* out = (float*)d_out;
    (void)in_sizes; (void)n_in; (void)out_size;

    const int AGG_SMEM = (48 * 256 + 48 * 48) * 4 + 48 * 8;   // 58752

    cudaFuncSetAttribute(proj_mma_kernel, cudaFuncAttributeMaxDynamicSharedMemorySize, PROJ_SMEM);
    cudaFuncSetAttribute(agg_kernel<0>, cudaFuncAttributeMaxDynamicSharedMemorySize, AGG_SMEM);
    cudaFuncSetAttribute(agg_kernel<1>, cudaFuncAttributeMaxDynamicSharedMemorySize, AGG_SMEM);
    cudaFuncSetAttribute(agg_kernel<2>, cudaFuncAttributeMaxDynamicSharedMemorySize, AGG_SMEM);

    w_split_kernel<<<320, 256>>>(Wq, Wk, Wv);
    proj_mma_kernel<<<dim3(2, NP / 128), 256, PROJ_SMEM>>>(query, bq, bk, bv);
    logits_kernel <<<dim3(WD, 3, BB), 256>>>();
    mz_kernel     <<<NP / 32, 256>>>();
    agg_kernel<0> <<<dim3(WD, BB), 512, AGG_SMEM>>>(query, gamma, out);
    agg_kernel<1> <<<dim3(WD, BB), 512, AGG_SMEM>>>(query, gamma, out);
    agg_kernel<2> <<<dim3(WD, BB), 512, AGG_SMEM>>>(query, gamma, out);
}

// round 8
// speedup vs baseline: 2.1108x; 1.0284x over previous
#include <cuda_runtime.h>
#include <cuda_fp16.h>
#include <math.h>
#include <stdint.h>

// Problem constants
#define BB   2
#define CC   256
#define EE   32
#define WD   2304      // W*D
#define HWD  110592    // H*W*D
#define NP   221184    // B*HWD
#define NL   144       // 3*48 logits per position

// ---------------------------------------------------------------------------
// Scratch (device globals: allocation-free rule)
// ---------------------------------------------------------------------------
__device__ float  g_q  [(size_t)NP * EE];
__device__ float  g_k  [(size_t)NP * EE];
__device__ __half g_v  [(size_t)NP * CC];     // fp16 storage (fp32 compute)
__device__ float  g_att[(size_t)NP * NL];     // raw logits fp32 (softmax path)
__device__ float2 g_mz [(size_t)NP];
__device__ __half g_acc[(size_t)NP * CC];     // fp16 partial sums
// W rows: 0..255 = Wv, 256..287 = Wq, 288..319 = Wk  (fp16 hi/lo split)
__device__ __half g_wh [320 * 256];
__device__ __half g_wl [320 * 256];

__device__ __forceinline__ uint32_t smem_u32(const void* p) {
    uint32_t a;
    asm("{ .reg .u64 t; cvta.to.shared.u64 t, %1; cvt.u32.u64 %0, t; }"
        : "=r"(a) : "l"(p));
    return a;
}

__device__ __forceinline__ uint32_t pack_h2(__half a, __half b) {
    __half2 h = __halves2half2(a, b);
    return *(uint32_t*)&h;
}

#define LDSM_T(r, addr) \
    asm volatile("ldmatrix.sync.aligned.m8n8.x4.trans.shared.b16 {%0,%1,%2,%3}, [%4];" \
                 : "=r"((r)[0]), "=r"((r)[1]), "=r"((r)[2]), "=r"((r)[3]) : "r"(addr))
#define LDSM_N(r, addr) \
    asm volatile("ldmatrix.sync.aligned.m8n8.x4.shared.b16 {%0,%1,%2,%3}, [%4];" \
                 : "=r"((r)[0]), "=r"((r)[1]), "=r"((r)[2]), "=r"((r)[3]) : "r"(addr))
#define MMA_F16(c, a, b0, b1) \
    asm volatile("mma.sync.aligned.m16n8k16.row.col.f32.f16.f16.f32 " \
                 "{%0,%1,%2,%3}, {%4,%5,%6,%7}, {%8,%9}, {%0,%1,%2,%3};" \
                 : "+f"((c)[0]), "+f"((c)[1]), "+f"((c)[2]), "+f"((c)[3]) \
                 : "r"((a)[0]), "r"((a)[1]), "r"((a)[2]), "r"((a)[3]), \
                   "r"(b0), "r"(b1))
#define CP16(dst, src) \
    asm volatile("cp.async.cg.shared.global [%0], [%1], 16;" :: "r"(dst), "l"(src))
#define CP_COMMIT() asm volatile("cp.async.commit_group;")
#define CP_WAIT0()  asm volatile("cp.async.wait_group 0;" ::: "memory")

// ---------------------------------------------------------------------------
// Kernel 0: split W into fp16 hi/lo
// ---------------------------------------------------------------------------
__global__ __launch_bounds__(256) void w_split_kernel(
    const float* __restrict__ Wq, const float* __restrict__ Wk,
    const float* __restrict__ Wv)
{
    const int r = blockIdx.x;
    const int c = threadIdx.x;
    const float w = (r < 256) ? Wv[r * 256 + c]
                  : (r < 288) ? Wq[(r - 256) * 256 + c]
                              : Wk[(r - 288) * 256 + c];
    const __half h = __float2half_rn(w);
    const __half l = __float2half_rn(w - __half2float(h));
    g_wh[r * 256 + c] = h;
    g_wl[r * 256 + c] = l;
}

// ---------------------------------------------------------------------------
// Fused QKV projection GEMM via mma.sync fp16.
//   V rows (o<256): 2 terms  Ah*W + Al*W      (W single fp16)
//   QK rows (o>=256): 3 terms Ah*Wh + Ah*Wl + Al*Wh
// Grid (2, NP/128): block bx covers output rows [bx*160, bx*160+160).
// CTA tile: 128 positions x 160 outputs, K = 256 in 8 stages of 32.
// ---------------------------------------------------------------------------
#define NROWS 160
#define NT    10
#define WN    80
#define ABUF  (32 * 136 * 2)
#define BBUF  (NROWS * 40 * 2)
#define PROJ_SMEM (4 * ABUF + 4 * BBUF)   // 86016 B

__global__ __launch_bounds__(256, 1) void proj_mma_kernel(
    const float* __restrict__ query,
    const float* __restrict__ bq, const float* __restrict__ bk,
    const float* __restrict__ bv)
{
    extern __shared__ char sm[];
    const uint32_t A_H = smem_u32(sm);
    const uint32_t A_L = A_H + 2 * ABUF;
    const uint32_t B_H = A_H + 4 * ABUF;
    const uint32_t B_L = B_H + 2 * BBUF;

    __shared__ float s_bias[NROWS];

    const int tid  = threadIdx.x;
    const int lane = tid & 31;
    const int warp = tid >> 5;
    const int wm   = warp & 3;
    const int wn   = warp >> 2;
    const int g    = lane >> 2;
    const int tg   = lane & 3;

    const int ob = (int)blockIdx.x * NROWS;
    const size_t pos0 = (size_t)blockIdx.y * 128;
    const int b  = (int)(pos0 / HWD);
    const int p0 = (int)(pos0 % HWD);
    const float* Xb = query + (size_t)b * CC * HWD + p0;

    if (tid < NROWS) {
        const int o = ob + tid;
        s_bias[tid] = (o < 256) ? bv[o] : (o < 288) ? bq[o - 256] : bk[o - 288];
    }

    const int aRowL = ((lane >> 4) << 3) + (lane & 7);
    const int aColL = ((lane >> 3) & 1) * 8;
    const int bRowL = aRowL;
    const int bColL = aColL;

    float acc[2][NT][4];
    #pragma unroll
    for (int mt = 0; mt < 2; mt++)
        #pragma unroll
        for (int nt = 0; nt < NT; nt++)
            #pragma unroll
            for (int i = 0; i < 4; i++) acc[mt][nt][i] = 0.f;

    float4 xa[4];

    auto ldga = [&](int t) {
        const int k0 = t * 32;
        #pragma unroll
        for (int j = 0; j < 4; j++) {
            const int f  = tid + j * 256;
            const int kr = f >> 5;
            const int p4 = (f & 31) * 4;
            xa[j] = *(const float4*)(Xb + (size_t)(k0 + kr) * HWD + p4);
        }
    };
    auto stsa = [&](int buf) {
        #pragma unroll
        for (int j = 0; j < 4; j++) {
            const int f  = tid + j * 256;
            const int kr = f >> 5;
            const int p4 = (f & 31) * 4;
            const float xs[4] = {xa[j].x, xa[j].y, xa[j].z, xa[j].w};
            __half h[4], l[4];
            #pragma unroll
            for (int e = 0; e < 4; e++) {
                h[e] = __float2half_rn(xs[e]);
                l[e] = __float2half_rn(xs[e] - __half2float(h[e]));
            }
            const uint32_t off = (uint32_t)(kr * 136 + p4) * 2;
            uint32_t dh = A_H + buf * ABUF + off;
            uint32_t dl = A_L + buf * ABUF + off;
            uint2 vh = make_uint2(pack_h2(h[0], h[1]), pack_h2(h[2], h[3]));
            uint2 vl = make_uint2(pack_h2(l[0], l[1]), pack_h2(l[2], l[3]));
            asm volatile("st.shared.v2.u32 [%0], {%1,%2};" :: "r"(dh), "r"(vh.x), "r"(vh.y));
            asm volatile("st.shared.v2.u32 [%0], {%1,%2};" :: "r"(dl), "r"(vl.x), "r"(vl.y));
        }
    };
    auto cpb = [&](int t, int buf) {
        const int k0 = t * 32;
        for (int id = tid; id < NROWS * 4; id += 256) {
            const int row = id >> 2;
            const int seg = id & 3;
            const uint32_t doff = (uint32_t)(row * 40 + seg * 8) * 2;
            CP16(B_H + buf * BBUF + doff, &g_wh[(size_t)(ob + row) * 256 + k0 + seg * 8]);
            if (ob + row >= 256)   // lo term only needed for QK rows
                CP16(B_L + buf * BBUF + doff, &g_wl[(size_t)(ob + row) * 256 + k0 + seg * 8]);
        }
    };
    auto compute = [&](int buf) {
        #pragma unroll
        for (int k16 = 0; k16 < 32; k16 += 16) {
            uint32_t ah[2][4], al[2][4];
            #pragma unroll
            for (int mt = 0; mt < 2; mt++) {
                const uint32_t off =
                    (uint32_t)((k16 + aRowL) * 136 + wm * 32 + mt * 16 + aColL) * 2;
                LDSM_T(ah[mt], A_H + buf * ABUF + off);
                LDSM_T(al[mt], A_L + buf * ABUF + off);
            }
            #pragma unroll
            for (int np = 0; np < NT / 2; np++) {
                const bool isQK = (ob + wn * WN + np * 16) >= 256;
                const uint32_t off =
                    (uint32_t)((wn * WN + np * 16 + bRowL) * 40 + k16 + bColL) * 2;
                uint32_t bh[4], bl[4];
                LDSM_N(bh, B_H + buf * BBUF + off);
                if (isQK) { LDSM_N(bl, B_L + buf * BBUF + off); }
                #pragma unroll
                for (int mt = 0; mt < 2; mt++)
                    #pragma unroll
                    for (int h = 0; h < 2; h++) {
                        const int nt = np * 2 + h;
                        MMA_F16(acc[mt][nt], ah[mt], bh[h*2], bh[h*2+1]);
                        MMA_F16(acc[mt][nt], al[mt], bh[h*2], bh[h*2+1]);
                        if (isQK)
                            MMA_F16(acc[mt][nt], ah[mt], bl[h*2], bl[h*2+1]);
                    }
            }
        }
    };

    ldga(0);
    cpb(0, 0);
    CP_COMMIT();
    stsa(0);
    CP_WAIT0();
    __syncthreads();

    #pragma unroll 1
    for (int t = 0; t < 8; t++) {
        if (t < 7) {
            ldga(t + 1);
            cpb(t + 1, (t + 1) & 1);
            CP_COMMIT();
        }
        compute(t & 1);
        if (t < 7) stsa((t + 1) & 1);
        CP_WAIT0();
        __syncthreads();
    }

    // ---- epilogue: rows <256 -> g_v (fp16), <288 -> g_q, else -> g_k ----
    #pragma unroll
    for (int mt = 0; mt < 2; mt++) {
        const size_t prow = pos0 + wm * 32 + mt * 16 + g;
        #pragma unroll
        for (int nt = 0; nt < NT; nt++) {
            const int nl = wn * WN + nt * 8 + tg * 2;
            const int n  = ob + nl;
            const float b0 = s_bias[nl], b1 = s_bias[nl + 1];
            if (n < 256) {
                *(__half2*)&g_v[prow * CC + n] =
                    __floats2half2_rn(acc[mt][nt][0] + b0, acc[mt][nt][1] + b1);
                *(__half2*)&g_v[(prow + 8) * CC + n] =
                    __floats2half2_rn(acc[mt][nt][2] + b0, acc[mt][nt][3] + b1);
            } else if (n < 288) {
                *(float2*)&g_q[prow * EE + n - 256] =
                    make_float2(acc[mt][nt][0] + b0, acc[mt][nt][1] + b1);
                *(float2*)&g_q[(prow + 8) * EE + n - 256] =
                    make_float2(acc[mt][nt][2] + b0, acc[mt][nt][3] + b1);
            } else {
                *(float2*)&g_k[prow * EE + n - 288] =
                    make_float2(acc[mt][nt][0] + b0, acc[mt][nt][1] + b1);
                *(float2*)&g_k[(prow + 8) * EE + n - 288] =
                    make_float2(acc[mt][nt][2] + b0, acc[mt][nt][3] + b1);
            }
        }
    }
}

// ---------------------------------------------------------------------------
// Kernel 2: raw logits per axis (q.k over 48-line), eH diagonal masked.
// ---------------------------------------------------------------------------
__global__ __launch_bounds__(256) void logits_kernel()
{
    const int l    = blockIdx.x;
    const int axis = blockIdx.y;
    const int b    = blockIdx.z;
    const int tid  = threadIdx.x;

    __shared__ float Qs[48][33];
    __shared__ float Ks[48][33];

    const int a1 = l / 48, a2 = l % 48;
    int base, stride;
    if      (axis == 0) { base = a1 * 48 + a2;      stride = WD; }
    else if (axis == 1) { base = a1 * WD + a2;      stride = 48; }
    else                { base = a1 * WD + a2 * 48; stride = 1;  }

    const size_t b0 = (size_t)b * HWD;

    for (int f = tid; f < 48 * 32; f += 256) {
        const int y = f >> 5, e = f & 31;
        const size_t p = b0 + base + (size_t)y * stride;
        Qs[y][e] = g_q[p * EE + e];
        Ks[y][e] = g_k[p * EE + e];
    }
    __syncthreads();

    const int xg = tid >> 4;
    const int yg = tid & 15;

    float acc[3][3];
    #pragma unroll
    for (int i = 0; i < 3; i++)
        #pragma unroll
        for (int j = 0; j < 3; j++) acc[i][j] = 0.f;

    #pragma unroll
    for (int e = 0; e < 32; e++) {
        float qv[3], kv[3];
        #pragma unroll
        for (int i = 0; i < 3; i++) qv[i] = Qs[xg + 16 * i][e];
        #pragma unroll
        for (int j = 0; j < 3; j++) kv[j] = Ks[yg + 16 * j][e];
        #pragma unroll
        for (int i = 0; i < 3; i++)
            #pragma unroll
            for (int j = 0; j < 3; j++)
                acc[i][j] += qv[i] * kv[j];
    }

    #pragma unroll
    for (int i = 0; i < 3; i++) {
        const int x = xg + 16 * i;
        const size_t p = b0 + base + (size_t)x * stride;
        float* dst = &g_att[p * NL + axis * 48];
        #pragma unroll
        for (int j = 0; j < 3; j++) {
            const int y = yg + 16 * j;
            dst[y] = (axis == 0 && x == y) ? -3.0e38f : acc[i][j];
        }
    }
}

// ---------------------------------------------------------------------------
// Kernel 3: per-position softmax stats (max, 1/sum) over 144 logits.
// ---------------------------------------------------------------------------
__global__ __launch_bounds__(256) void mz_kernel()
{
    const int tid  = threadIdx.x;
    const int pos  = blockIdx.x * 32 + (tid >> 3);
    const int lane = tid & 7;
    const float* row = g_att + (size_t)pos * NL;

    float4 v[5];
    float m = -3.4e38f;
    #pragma unroll
    for (int k = 0; k < 5; k++) {
        const int j = lane + k * 8;
        if (j < 36) {
            v[k] = *(const float4*)&row[j * 4];
            m = fmaxf(m, fmaxf(fmaxf(v[k].x, v[k].y), fmaxf(v[k].z, v[k].w)));
        }
    }
    #pragma unroll
    for (int o = 1; o < 8; o <<= 1)
        m = fmaxf(m, __shfl_xor_sync(0xffffffffu, m, o));

    float s = 0.f;
    #pragma unroll
    for (int k = 0; k < 5; k++) {
        const int j = lane + k * 8;
        if (j < 36) {
            s += expf(v[k].x - m) + expf(v[k].y - m)
               + expf(v[k].z - m) + expf(v[k].w - m);
        }
    }
    #pragma unroll
    for (int o = 1; o < 8; o <<= 1)
        s += __shfl_xor_sync(0xffffffffu, s, o);

    if (lane == 0) g_mz[pos] = make_float2(m, 1.f / s);
}

// ---------------------------------------------------------------------------
// Kernel 4/5/6: aggregation per axis (normalizes logits on the fly).
// g_v / g_acc stored fp16; all compute fp32.
// ---------------------------------------------------------------------------
template<int AXIS>
__global__ __launch_bounds__(512) void agg_kernel(
    const float* __restrict__ query,
    const float* __restrict__ gamma,
    float* __restrict__ out)
{
    extern __shared__ float smf[];
    float  (*Vs)[256] = (float (*)[256])smf;              // 48x256
    float  (*As)[48]  = (float (*)[48])(smf + 48 * 256);  // 48x48
    float2* mzs       = (float2*)(smf + 48 * 256 + 48 * 48);

    const int l   = blockIdx.x;
    const int b   = blockIdx.y;
    const int tid = threadIdx.x;

    const int a1 = l / 48, a2 = l % 48;
    int base, stride;
    if      (AXIS == 0) { base = a1 * 48 + a2;      stride = WD; }
    else if (AXIS == 1) { base = a1 * WD + a2;      stride = 48; }
    else                { base = a1 * WD + a2 * 48; stride = 1;  }

    const size_t b0 = (size_t)b * HWD;

    if (tid < 48) mzs[tid] = g_mz[b0 + base + (size_t)tid * stride];

    // load V line (48 x 256 fp16 -> fp32 smem): 1536 uint4 (8 halves each)
    #pragma unroll
    for (int k = 0; k < 3; k++) {
        const int f  = tid + k * 512;
        const int y  = f >> 5;
        const int c8 = (f & 31) * 8;
        const uint4 raw = *(const uint4*)&g_v[(b0 + base + (size_t)y * stride) * CC + c8];
        const __half2* hp = (const __half2*)&raw;
        #pragma unroll
        for (int q = 0; q < 4; q++) {
            const float2 f2 = __half22float2(hp[q]);
            Vs[y][c8 + q * 2]     = f2.x;
            Vs[y][c8 + q * 2 + 1] = f2.y;
        }
    }
    __syncthreads();

    for (int f = tid; f < 48 * 48; f += 512) {
        const int x = f / 48, y = f % 48;
        const float raw = g_att[(b0 + base + (size_t)x * stride) * NL + AXIS * 48 + y];
        const float2 mz = mzs[x];
        As[x][y] = expf(raw - mz.x) * mz.y;
    }
    __syncthreads();

    const int cg = tid & 31;
    const int ca = cg * 4;
    const int xg = tid >> 5;
    const int x0 = xg * 3;

    float acc[3][8];
    #pragma unroll
    for (int i = 0; i < 3; i++)
        #pragma unroll
        for (int j = 0; j < 8; j++) acc[i][j] = 0.f;

    #pragma unroll 2
    for (int y = 0; y < 48; y++) {
        const float4 v0 = *(const float4*)&Vs[y][ca];
        const float4 v1 = *(const float4*)&Vs[y][ca + 128];
        #pragma unroll
        for (int xi = 0; xi < 3; xi++) {
            const float a = As[x0 + xi][y];
            acc[xi][0] += a * v0.x; acc[xi][1] += a * v0.y;
            acc[xi][2] += a * v0.z; acc[xi][3] += a * v0.w;
            acc[xi][4] += a * v1.x; acc[xi][5] += a * v1.y;
            acc[xi][6] += a * v1.z; acc[xi][7] += a * v1.w;
        }
    }

    if (AXIS == 0) {
        #pragma unroll
        for (int xi = 0; xi < 3; xi++) {
            const size_t p = b0 + base + (size_t)(x0 + xi) * stride;
            *(__half2*)&g_acc[p * CC + ca]           = __floats2half2_rn(acc[xi][0], acc[xi][1]);
            *(__half2*)&g_acc[p * CC + ca + 2]       = __floats2half2_rn(acc[xi][2], acc[xi][3]);
            *(__half2*)&g_acc[p * CC + ca + 128]     = __floats2half2_rn(acc[xi][4], acc[xi][5]);
            *(__half2*)&g_acc[p * CC + ca + 130]     = __floats2half2_rn(acc[xi][6], acc[xi][7]);
        }
    } else if (AXIS == 1) {
        #pragma unroll
        for (int xi = 0; xi < 3; xi++) {
            const size_t p = b0 + base + (size_t)(x0 + xi) * stride;
            __half2* d0 = (__half2*)&g_acc[p * CC + ca];
            __half2* d1 = (__half2*)&g_acc[p * CC + ca + 128];
            const float2 a0 = __half22float2(d0[0]);
            const float2 a1 = __half22float2(d0[1]);
            const float2 a2 = __half22float2(d1[0]);
            const float2 a3 = __half22float2(d1[1]);
            d0[0] = __floats2half2_rn(acc[xi][0] + a0.x, acc[xi][1] + a0.y);
            d0[1] = __floats2half2_rn(acc[xi][2] + a1.x, acc[xi][3] + a1.y);
            d1[0] = __floats2half2_rn(acc[xi][4] + a2.x, acc[xi][5] + a2.y);
            d1[1] = __floats2half2_rn(acc[xi][6] + a3.x, acc[xi][7] + a3.y);
        }
    } else {
        __syncthreads();
        float (*Rs)[256] = Vs;
        #pragma unroll
        for (int xi = 0; xi < 3; xi++) {
            const int x = x0 + xi;
            const size_t p = b0 + base + x;     // stride 1
            const __half2* s0 = (const __half2*)&g_acc[p * CC + ca];
            const __half2* s1 = (const __half2*)&g_acc[p * CC + ca + 128];
            const float2 a0 = __half22float2(s0[0]);
            const float2 a1 = __half22float2(s0[1]);
            const float2 a2 = __half22float2(s1[0]);
            const float2 a3 = __half22float2(s1[1]);
            Rs[x][ca + 0]   = acc[xi][0] + a0.x;  Rs[x][ca + 1]   = acc[xi][1] + a0.y;
            Rs[x][ca + 2]   = acc[xi][2] + a1.x;  Rs[x][ca + 3]   = acc[xi][3] + a1.y;
            Rs[x][ca + 128] = acc[xi][4] + a2.x;  Rs[x][ca + 129] = acc[xi][5] + a2.y;
            Rs[x][ca + 130] = acc[xi][6] + a3.x;  Rs[x][ca + 131] = acc[xi][7] + a3.y;
        }
        __syncthreads();

        const float gm = gamma[0];
        const int c  = tid & 255;
        const int xh = tid >> 8;
        const size_t gidx = ((size_t)b * CC + c) * HWD + base;
        #pragma unroll 4
        for (int x = xh * 24; x < xh * 24 + 24; x++) {
            out[gidx + x] = gm * Rs[x][c] + query[gidx + x];
        }
    }
}

// ---------------------------------------------------------------------------
extern "C" void kernel_launch(void* const* d_in, const int* in_sizes, int n_in,
                              void* d_out, int out_size)
{
    const float* query = (const float*)d_in[0];
    const float* Wq    = (const float*)d_in[1];
    const float* bq    = (const float*)d_in[2];
    const float* Wk    = (const float*)d_in[3];
    const float* bk    = (const float*)d_in[4];
    const float* Wv    = (const float*)d_in[5];
    const float* bv    = (const float*)d_in[6];
    const float* gamma = (const float*)d_in[7];
    float* out = (float*)d_out;
    (void)in_sizes; (void)n_in; (void)out_size;

    const int AGG_SMEM = (48 * 256 + 48 * 48) * 4 + 48 * 8;   // 58752

    cudaFuncSetAttribute(proj_mma_kernel, cudaFuncAttributeMaxDynamicSharedMemorySize, PROJ_SMEM);
    cudaFuncSetAttribute(agg_kernel<0>, cudaFuncAttributeMaxDynamicSharedMemorySize, AGG_SMEM);
    cudaFuncSetAttribute(agg_kernel<1>, cudaFuncAttributeMaxDynamicSharedMemorySize, AGG_SMEM);
    cudaFuncSetAttribute(agg_kernel<2>, cudaFuncAttributeMaxDynamicSharedMemorySize, AGG_SMEM);

    w_split_kernel<<<320, 256>>>(Wq, Wk, Wv);
    proj_mma_kernel<<<dim3(2, NP / 128), 256, PROJ_SMEM>>>(query, bq, bk, bv);
    logits_kernel <<<dim3(WD, 3, BB), 256>>>();
    mz_kernel     <<<NP / 32, 256>>>();
    agg_kernel<0> <<<dim3(WD, BB), 512, AGG_SMEM>>>(query, gamma, out);
    agg_kernel<1> <<<dim3(WD, BB), 512, AGG_SMEM>>>(query, gamma, out);
    agg_kernel<2> <<<dim3(WD, BB), 512, AGG_SMEM>>>(query, gamma, out);
}